// round 2
// baseline (speedup 1.0000x reference)
#include <cuda_runtime.h>
#include <math.h>

// ---------------- problem constants ----------------
#define BB 32
#define SS 512
#define DM 512
#define NH 8
#define DK 64
#define DINNER 2048
#define MTOT (BB * SS)              // 16384 rows
#define ENC_ELEMS (BB * SS * DM)    // 8388608
#define EPSLN 1e-3f

// ---------------- scratch (device globals; no allocation allowed) ----------------
__device__ float g_xc[MTOT * DM];        // compacted input      33.5 MB
__device__ float g_q[MTOT * DM];         // [b,s,h,k]            33.5 MB
__device__ float g_k[MTOT * DM];
__device__ float g_v[MTOT * DM];
__device__ float g_heads[MTOT * DM];     // attn heads concat
__device__ float g_tmp[MTOT * DM];       // pre-LN gemm out (reused)
__device__ float g_attnout[MTOT * DM];   // LN1 output
__device__ float g_ffnh[MTOT * DINNER];  // FFN hidden          134 MB
__device__ float g_wq[DM * DM];          // packed [d, h*64+k]
__device__ float g_wk[DM * DM];
__device__ float g_wv[DM * DM];
__device__ int   g_idx[BB * SS];
__device__ int   g_nkeep[BB];

// ---------------- skipper: stable compaction scan ----------------
__global__ void skipper_scan(const int* __restrict__ keep, int* __restrict__ idx,
                             int* __restrict__ nkeep) {
    int b = blockIdx.x, t = threadIdx.x;  // 512 threads
    __shared__ int sh[SS];
    int v = keep[b * SS + t] > 0;
    sh[t] = v;
    __syncthreads();
    for (int off = 1; off < SS; off <<= 1) {
        int x = (t >= off) ? sh[t - off] : 0;
        __syncthreads();
        sh[t] += x;
        __syncthreads();
    }
    int incl = sh[t];
    if (v) idx[b * SS + incl - 1] = t;
    if (t == SS - 1) nkeep[b] = incl;
}

// gather compacted rows, zero the tail
__global__ void gather_kernel(const float* __restrict__ x, const int* __restrict__ idx,
                              const int* __restrict__ nkeep, float* __restrict__ xc) {
    int bs = blockIdx.x;
    int b = bs >> 9, s = bs & 511;
    int nk = nkeep[b];
    float4* o = (float4*)(xc + (size_t)bs * DM);
    if (s < nk) {
        const float4* src = (const float4*)(x + ((size_t)b * SS + idx[b * SS + s]) * DM);
        o[threadIdx.x] = src[threadIdx.x];  // 128 thr * 4 = 512
    } else {
        o[threadIdx.x] = make_float4(0.f, 0.f, 0.f, 0.f);
    }
}

// pack per-head weight [H, D, 64] -> [D, H*64]
__global__ void pack_w(const float* __restrict__ w, float* __restrict__ wp) {
    int i = blockIdx.x * 256 + threadIdx.x;  // over 512*512
    int d = i >> 9;
    int n = i & 511;
    int h = n >> 6, kk = n & 63;
    wp[i] = w[(h * DM + d) * DK + kk];
}

// ---------------- classic fp32 SGEMM 128x128x8, 8x8 per thread ----------------
// C[M,N] = A[M,K] @ B[K,N] (+bias per-col, optional relu). M%128==0, N%128==0, K%8==0.
__global__ void __launch_bounds__(256) sgemm_kernel(
    const float* __restrict__ A, const float* __restrict__ B, float* __restrict__ C,
    int M, int N, int K, const float* __restrict__ bias, int relu) {
    __shared__ float As[8][128];
    __shared__ float Bs[8][128];
    int tid = threadIdx.x;
    int brow = blockIdx.y * 128, bcol = blockIdx.x * 128;
    int arow = tid >> 1;             // 0..127
    int acol = (tid & 1) * 4;        // 0 or 4
    int brl = tid >> 5;              // 0..7
    int bcl = (tid & 31) * 4;        // 0..124
    int tx = tid & 15, ty = tid >> 4;
    float acc[8][8];
#pragma unroll
    for (int i = 0; i < 8; i++)
#pragma unroll
        for (int j = 0; j < 8; j++) acc[i][j] = 0.f;

    const float* Ap = A + (size_t)(brow + arow) * K + acol;
    const float* Bp = B + (size_t)brl * N + bcol + bcl;
    for (int k0 = 0; k0 < K; k0 += 8) {
        float4 a4 = *(const float4*)(Ap + k0);
        As[acol + 0][arow] = a4.x;
        As[acol + 1][arow] = a4.y;
        As[acol + 2][arow] = a4.z;
        As[acol + 3][arow] = a4.w;
        float4 b4 = *(const float4*)(Bp + (size_t)k0 * N);
        *(float4*)(&Bs[brl][bcl]) = b4;
        __syncthreads();
#pragma unroll
        for (int kk = 0; kk < 8; kk++) {
            float ar[8], br[8];
#pragma unroll
            for (int i = 0; i < 8; i++) ar[i] = As[kk][ty * 8 + i];
#pragma unroll
            for (int j = 0; j < 8; j++) br[j] = Bs[kk][tx * 8 + j];
#pragma unroll
            for (int i = 0; i < 8; i++)
#pragma unroll
                for (int j = 0; j < 8; j++) acc[i][j] += ar[i] * br[j];
        }
        __syncthreads();
    }
#pragma unroll
    for (int i = 0; i < 8; i++) {
        int r = brow + ty * 8 + i;
#pragma unroll
        for (int j = 0; j < 8; j++) {
            int c = bcol + tx * 8 + j;
            float v = acc[i][j];
            if (bias) v += bias[c];
            if (relu) v = fmaxf(v, 0.f);
            C[(size_t)r * N + c] = v;
        }
    }
}

// ---------------- fused attention: scores -> softmax -> write P -> P@V ----------------
// block: (b,h) x 32-row tile of s.  256 threads. q/k/v layout [b,s,h*64+k].
__global__ void __launch_bounds__(256) attention_kernel(
    const float* __restrict__ q, const float* __restrict__ k, const float* __restrict__ v,
    const int* __restrict__ nkeep, float* __restrict__ attns, float* __restrict__ heads) {
    extern __shared__ float sm[];
    float* Ss = sm;                 // 32*512
    float* Ks = sm + 32 * 512;      // 64*65 (reused for V)
    float* Qs = Ks + 64 * 65;       // 32*65
    int bh = blockIdx.x;
    int b = bh >> 3, h = bh & 7;
    int s0 = blockIdx.y * 32;
    int tid = threadIdx.x;
    int nk = nkeep[b];
    const float inv_temp = 0.04419417382415922f;  // 1/sqrt(512)

    for (int i = tid; i < 32 * 64; i += 256) {
        int r = i >> 6, kk = i & 63;
        Qs[r * 65 + kk] = q[((size_t)(b * SS + s0 + r)) * DM + h * 64 + kk];
    }
    int r = tid >> 3, cg = tid & 7;

    for (int t0 = 0; t0 < SS; t0 += 64) {
        __syncthreads();
        for (int i = tid; i < 64 * 64; i += 256) {
            int tt = i >> 6, kk = i & 63;
            Ks[tt * 65 + kk] = k[((size_t)(b * SS + t0 + tt)) * DM + h * 64 + kk];
        }
        __syncthreads();
        float acc[8];
#pragma unroll
        for (int j = 0; j < 8; j++) acc[j] = 0.f;
#pragma unroll
        for (int kk = 0; kk < 64; kk++) {
            float a = Qs[r * 65 + kk];
#pragma unroll
            for (int j = 0; j < 8; j++) acc[j] += a * Ks[(cg * 8 + j) * 65 + kk];
        }
#pragma unroll
        for (int j = 0; j < 8; j++) {
            int t = t0 + cg * 8 + j;
            Ss[r * 512 + t] = (t < nk) ? acc[j] * inv_temp : -INFINITY;
        }
    }
    __syncthreads();

    // softmax: 8 threads per row; thread owns 64 contiguous cols
    {
        float m = -INFINITY;
        for (int i = 0; i < 64; i++) m = fmaxf(m, Ss[r * 512 + cg * 64 + i]);
        for (int o = 1; o < 8; o <<= 1) m = fmaxf(m, __shfl_xor_sync(~0u, m, o));
        float sum = 0.f;
        for (int i = 0; i < 64; i++) {
            float e = __expf(Ss[r * 512 + cg * 64 + i] - m);
            Ss[r * 512 + cg * 64 + i] = e;
            sum += e;
        }
        for (int o = 1; o < 8; o <<= 1) sum += __shfl_xor_sync(~0u, sum, o);
        float inv = 1.f / sum;
        for (int i = 0; i < 64; i++) Ss[r * 512 + cg * 64 + i] *= inv;
    }
    __syncthreads();

    // write P to attns region: index [h*B + b][s][t]
    {
        float* dst = attns + (((size_t)(h * BB + b)) * SS + s0) * SS;
        for (int i = tid; i < 32 * 512; i += 256) dst[i] = Ss[i];
    }

    // O = P @ V
    float o[8];
#pragma unroll
    for (int j = 0; j < 8; j++) o[j] = 0.f;
    for (int t0 = 0; t0 < SS; t0 += 64) {
        __syncthreads();
        for (int i = tid; i < 64 * 64; i += 256) {
            int tt = i >> 6, vv = i & 63;
            Ks[tt * 65 + vv] = v[((size_t)(b * SS + t0 + tt)) * DM + h * 64 + vv];
        }
        __syncthreads();
#pragma unroll
        for (int tt = 0; tt < 64; tt++) {
            float p = Ss[r * 512 + t0 + tt];
#pragma unroll
            for (int j = 0; j < 8; j++) o[j] += p * Ks[tt * 65 + cg * 8 + j];
        }
    }
#pragma unroll
    for (int j = 0; j < 8; j++)
        heads[((size_t)(b * SS + s0 + r)) * DM + h * 64 + cg * 8 + j] = o[j];
}

// ---------------- layernorm (unbiased var, eps added to std) with residual ----------------
__global__ void ln_kernel(const float* __restrict__ y, const float* __restrict__ resid,
                          const float* __restrict__ g, const float* __restrict__ be,
                          float* __restrict__ out) {
    int row = blockIdx.x;
    int tid = threadIdx.x;  // 128
    float4 a = ((const float4*)(y + (size_t)row * DM))[tid];
    float4 b = ((const float4*)(resid + (size_t)row * DM))[tid];
    float v0 = a.x + b.x, v1 = a.y + b.y, v2 = a.z + b.z, v3 = a.w + b.w;
    float s = v0 + v1 + v2 + v3;
    float ss = v0 * v0 + v1 * v1 + v2 * v2 + v3 * v3;
    for (int o = 16; o; o >>= 1) {
        s += __shfl_xor_sync(~0u, s, o);
        ss += __shfl_xor_sync(~0u, ss, o);
    }
    __shared__ float shs[4], shss[4];
    int w = tid >> 5, l = tid & 31;
    if (l == 0) { shs[w] = s; shss[w] = ss; }
    __syncthreads();
    s = shs[0] + shs[1] + shs[2] + shs[3];
    ss = shss[0] + shss[1] + shss[2] + shss[3];
    float mu = s * (1.f / 512.f);
    float var = fmaxf((ss - 512.f * mu * mu) * (1.f / 511.f), 0.f);
    float inv = 1.f / (sqrtf(var) + EPSLN);
    float4 gg = ((const float4*)g)[tid];
    float4 bb = ((const float4*)be)[tid];
    float4 o;
    o.x = (v0 - mu) * inv * gg.x + bb.x;
    o.y = (v1 - mu) * inv * gg.y + bb.y;
    o.z = (v2 - mu) * inv * gg.z + bb.z;
    o.w = (v3 - mu) * inv * gg.w + bb.w;
    ((float4*)(out + (size_t)row * DM))[tid] = o;
}

// ---------------- launch ----------------
extern "C" void kernel_launch(void* const* d_in, const int* in_sizes, int n_in,
                              void* d_out, int out_size) {
    const float* x      = (const float*)d_in[0];
    const float* w_qs   = (const float*)d_in[1];
    const float* w_ks   = (const float*)d_in[2];
    const float* w_vs   = (const float*)d_in[3];
    const float* proj_w = (const float*)d_in[4];
    const float* proj_b = (const float*)d_in[5];
    const float* ln1_g  = (const float*)d_in[6];
    const float* ln1_b  = (const float*)d_in[7];
    const float* ffn_w1 = (const float*)d_in[8];
    const float* ffn_b1 = (const float*)d_in[9];
    const float* ffn_w2 = (const float*)d_in[10];
    const float* ffn_b2 = (const float*)d_in[11];
    const float* ln2_g  = (const float*)d_in[12];
    const float* ln2_b  = (const float*)d_in[13];
    const int*   keepm  = (const int*)d_in[14];

    float* out = (float*)d_out;
    float* enc_out = out;                 // [B,S,D]
    float* attns   = out + ENC_ELEMS;     // [H*B,S,S]

    float *xc, *q, *k, *v, *heads, *tmp, *attn_out, *ffnh, *wq, *wk, *wv;
    int *idx, *nk;
    cudaGetSymbolAddress((void**)&xc, g_xc);
    cudaGetSymbolAddress((void**)&q, g_q);
    cudaGetSymbolAddress((void**)&k, g_k);
    cudaGetSymbolAddress((void**)&v, g_v);
    cudaGetSymbolAddress((void**)&heads, g_heads);
    cudaGetSymbolAddress((void**)&tmp, g_tmp);
    cudaGetSymbolAddress((void**)&attn_out, g_attnout);
    cudaGetSymbolAddress((void**)&ffnh, g_ffnh);
    cudaGetSymbolAddress((void**)&wq, g_wq);
    cudaGetSymbolAddress((void**)&wk, g_wk);
    cudaGetSymbolAddress((void**)&wv, g_wv);
    cudaGetSymbolAddress((void**)&idx, g_idx);
    cudaGetSymbolAddress((void**)&nk, g_nkeep);

    static int smem_set = 0;
    if (!smem_set) {
        cudaFuncSetAttribute(attention_kernel, cudaFuncAttributeMaxDynamicSharedMemorySize,
                             (32 * 512 + 64 * 65 + 32 * 65) * 4);
        smem_set = 1;
    }

    // 1. skipper
    skipper_scan<<<BB, SS>>>(keepm, idx, nk);
    gather_kernel<<<MTOT, 128>>>(x, idx, nk, xc);

    // 2. pack QKV weights
    pack_w<<<(DM * DM) / 256, 256>>>(w_qs, wq);
    pack_w<<<(DM * DM) / 256, 256>>>(w_ks, wk);
    pack_w<<<(DM * DM) / 256, 256>>>(w_vs, wv);

    // 3. QKV projections: [16384,512] @ [512,512]
    dim3 gproj(DM / 128, MTOT / 128);
    sgemm_kernel<<<gproj, 256>>>(xc, wq, q, MTOT, DM, DM, nullptr, 0);
    sgemm_kernel<<<gproj, 256>>>(xc, wk, k, MTOT, DM, DM, nullptr, 0);
    sgemm_kernel<<<gproj, 256>>>(xc, wv, v, MTOT, DM, DM, nullptr, 0);

    // 4. fused attention (writes attns + heads)
    dim3 gatt(BB * NH, SS / 32);
    attention_kernel<<<gatt, 256, (32 * 512 + 64 * 65 + 32 * 65) * 4>>>(q, k, v, nk, attns, heads);

    // 5. output projection + LN1
    sgemm_kernel<<<gproj, 256>>>(heads, proj_w, tmp, MTOT, DM, DM, proj_b, 0);
    ln_kernel<<<MTOT, 128>>>(tmp, xc, ln1_g, ln1_b, attn_out);

    // 6. FFN
    dim3 gff1(DINNER / 128, MTOT / 128);
    sgemm_kernel<<<gff1, 256>>>(attn_out, ffn_w1, ffnh, MTOT, DINNER, DM, ffn_b1, 1);
    sgemm_kernel<<<gproj, 256>>>(ffnh, ffn_w2, tmp, MTOT, DM, DINNER, ffn_b2, 0);
    ln_kernel<<<MTOT, 128>>>(tmp, attn_out, ln2_g, ln2_b, enc_out);
}

// round 3
// speedup vs baseline: 1.4787x; 1.4787x over previous
#include <cuda_runtime.h>
#include <math.h>
#include <stdint.h>

// ---------------- problem constants ----------------
#define BB 32
#define SS 512
#define DM 512
#define NH 8
#define DK 64
#define DINNER 2048
#define MTOT (BB * SS)              // 16384 rows
#define ENC_ELEMS (BB * SS * DM)    // 8388608
#define EPSLN 1e-3f

// ---------------- scratch (device globals; no allocation allowed) ----------------
__device__ float g_xc[MTOT * DM];          // compacted input
__device__ float g_qkv[MTOT * 3 * DM];     // merged q|k|v  [row][1536]
__device__ float g_heads[MTOT * DM];       // attn heads concat
__device__ float g_tmp[MTOT * DM];         // pre-LN gemm out (reused)
__device__ float g_attnout[MTOT * DM];     // LN1 output
__device__ float g_ffnh[MTOT * DINNER];    // FFN hidden
__device__ float g_wqkv[DM * 3 * DM];      // packed [d][1536]
__device__ int   g_idx[BB * SS];
__device__ int   g_nkeep[BB];

// ---------------- skipper: stable compaction scan ----------------
__global__ void skipper_scan(const int* __restrict__ keep, int* __restrict__ idx,
                             int* __restrict__ nkeep) {
    int b = blockIdx.x, t = threadIdx.x;  // 512 threads
    __shared__ int sh[SS];
    int v = keep[b * SS + t] > 0;
    sh[t] = v;
    __syncthreads();
    for (int off = 1; off < SS; off <<= 1) {
        int x = (t >= off) ? sh[t - off] : 0;
        __syncthreads();
        sh[t] += x;
        __syncthreads();
    }
    int incl = sh[t];
    if (v) idx[b * SS + incl - 1] = t;
    if (t == SS - 1) nkeep[b] = incl;
}

// gather compacted rows, zero the tail
__global__ void gather_kernel(const float* __restrict__ x, const int* __restrict__ idx,
                              const int* __restrict__ nkeep, float* __restrict__ xc) {
    int bs = blockIdx.x;
    int b = bs >> 9, s = bs & 511;
    int nk = nkeep[b];
    float4* o = (float4*)(xc + (size_t)bs * DM);
    if (s < nk) {
        const float4* src = (const float4*)(x + ((size_t)b * SS + idx[b * SS + s]) * DM);
        o[threadIdx.x] = src[threadIdx.x];  // 128 thr * 4 = 512
    } else {
        o[threadIdx.x] = make_float4(0.f, 0.f, 0.f, 0.f);
    }
}

// pack per-head weights [H, D, 64] x3 -> [D, 1536] (q | k | v, head-major cols)
__global__ void pack_wqkv(const float* __restrict__ wq, const float* __restrict__ wk,
                          const float* __restrict__ wv, float* __restrict__ wp) {
    int i = blockIdx.x * 256 + threadIdx.x;  // over 512*512
    int d = i >> 9;
    int n = i & 511;
    int h = n >> 6, kk = n & 63;
    int src = (h * DM + d) * DK + kk;
    wp[(size_t)d * 1536 + n]        = wq[src];
    wp[(size_t)d * 1536 + 512 + n]  = wk[src];
    wp[(size_t)d * 1536 + 1024 + n] = wv[src];
}

// ---------------- tf32 tensor-core GEMM ----------------
// C[M,N] = A[M,K] @ B[K,N] (+bias, optional relu).
// block tile 128x256, 8 warps, warp tile 64x64 (4 x m16, 8 x n8), BK=16,
// cp.async double buffer. M%128==0, N%256==0, K%16==0.
#define GBM 128
#define GBN 256
#define GBK 16
#define AS_STRIDE 20    // floats per A-row in smem (16 used) — conflict-free frags
#define BS_STRIDE 264   // floats per B-row in smem (256 used)
#define AS_ELEMS (GBM * AS_STRIDE)   // 2560
#define BS_ELEMS (GBK * BS_STRIDE)   // 4224
#define GSMEM_FLOATS (2 * (AS_ELEMS + BS_ELEMS))  // 13568 -> 54272 B

__device__ __forceinline__ uint32_t f2tf32(float f) {
    uint32_t u;
    asm("cvt.rna.tf32.f32 %0, %1;" : "=r"(u) : "f"(f));
    return u;
}
__device__ __forceinline__ void cpa16(uint32_t dst, const float* src) {
    asm volatile("cp.async.cg.shared.global [%0], [%1], 16;" :: "r"(dst), "l"(src));
}
__device__ __forceinline__ void mma_tf32(float* d, const uint32_t* a, const uint32_t* b) {
    asm volatile(
        "mma.sync.aligned.m16n8k8.row.col.f32.tf32.tf32.f32 "
        "{%0,%1,%2,%3}, {%4,%5,%6,%7}, {%8,%9}, {%0,%1,%2,%3};"
        : "+f"(d[0]), "+f"(d[1]), "+f"(d[2]), "+f"(d[3])
        : "r"(a[0]), "r"(a[1]), "r"(a[2]), "r"(a[3]), "r"(b[0]), "r"(b[1]));
}

__global__ void __launch_bounds__(256, 1) tc_gemm(
    const float* __restrict__ A, const float* __restrict__ B, float* __restrict__ C,
    int M, int N, int K, const float* __restrict__ bias, int relu) {
    extern __shared__ float sm[];
    float* As[2] = {sm, sm + AS_ELEMS};
    float* Bs[2] = {sm + 2 * AS_ELEMS, sm + 2 * AS_ELEMS + BS_ELEMS};
    uint32_t sbase = (uint32_t)__cvta_generic_to_shared(sm);

    int tid = threadIdx.x;
    int wid = tid >> 5, lane = tid & 31;
    int g = lane >> 2, t4 = lane & 3;
    int wm = wid >> 2, wn = wid & 3;          // 2 x 4 warp grid
    int rowBase = blockIdx.y * GBM;
    int colBase = blockIdx.x * GBN;

    // global load coords (fixed per thread)
    int ar = tid >> 2;            // A: two rows per thread (ar, ar+64)
    int ac4 = (tid & 3) * 4;
    int bkr = tid >> 6;           // B: rows bkr, bkr+4, bkr+8, bkr+12
    int bn4 = (tid & 63) * 4;

    const float* Arow0 = A + (size_t)(rowBase + ar) * K + ac4;
    const float* Arow1 = A + (size_t)(rowBase + ar + 64) * K + ac4;
    const float* Bbase = B + (size_t)bkr * N + colBase + bn4;

    float acc[4][8][4];
#pragma unroll
    for (int i = 0; i < 4; i++)
#pragma unroll
        for (int j = 0; j < 8; j++)
#pragma unroll
            for (int c = 0; c < 4; c++) acc[i][j][c] = 0.f;

    int nk = K / GBK;

    // prologue: load tile 0 into buf 0
    {
        uint32_t ad = sbase + (0 * AS_ELEMS + ar * AS_STRIDE + ac4) * 4;
        cpa16(ad, Arow0);
        cpa16(ad + 64 * AS_STRIDE * 4, Arow1);
        uint32_t bd = sbase + (2 * AS_ELEMS + bkr * BS_STRIDE + bn4) * 4;
#pragma unroll
        for (int i = 0; i < 4; i++)
            cpa16(bd + i * 4 * BS_STRIDE * 4, Bbase + (size_t)(i * 4) * N);
        asm volatile("cp.async.commit_group;");
    }

    for (int kt = 0; kt < nk; kt++) {
        if (kt + 1 < nk) {
            int buf = (kt + 1) & 1;
            int k0 = (kt + 1) * GBK;
            uint32_t ad = sbase + (buf * AS_ELEMS + ar * AS_STRIDE + ac4) * 4;
            cpa16(ad, Arow0 + k0);
            cpa16(ad + 64 * AS_STRIDE * 4, Arow1 + k0);
            uint32_t bd = sbase + ((2 * AS_ELEMS + buf * BS_ELEMS) + bkr * BS_STRIDE + bn4) * 4;
#pragma unroll
            for (int i = 0; i < 4; i++)
                cpa16(bd + i * 4 * BS_STRIDE * 4, Bbase + (size_t)(k0 + i * 4) * N);
            asm volatile("cp.async.commit_group;");
            asm volatile("cp.async.wait_group 1;");
        } else {
            asm volatile("cp.async.wait_group 0;");
        }
        __syncthreads();

        const float* as = As[kt & 1];
        const float* bs = Bs[kt & 1];
#pragma unroll
        for (int ks = 0; ks < 2; ks++) {
            uint32_t af[4][4];
#pragma unroll
            for (int mt = 0; mt < 4; mt++) {
                int m0 = wm * 64 + mt * 16;
                int kk = ks * 8 + t4;
                af[mt][0] = f2tf32(as[(m0 + g) * AS_STRIDE + kk]);
                af[mt][1] = f2tf32(as[(m0 + g + 8) * AS_STRIDE + kk]);
                af[mt][2] = f2tf32(as[(m0 + g) * AS_STRIDE + kk + 4]);
                af[mt][3] = f2tf32(as[(m0 + g + 8) * AS_STRIDE + kk + 4]);
            }
            uint32_t bf[8][2];
#pragma unroll
            for (int nt = 0; nt < 8; nt++) {
                int n0 = wn * 64 + nt * 8 + g;
                bf[nt][0] = f2tf32(bs[(ks * 8 + t4) * BS_STRIDE + n0]);
                bf[nt][1] = f2tf32(bs[(ks * 8 + t4 + 4) * BS_STRIDE + n0]);
            }
#pragma unroll
            for (int mt = 0; mt < 4; mt++)
#pragma unroll
                for (int nt = 0; nt < 8; nt++) mma_tf32(acc[mt][nt], af[mt], bf[nt]);
        }
        __syncthreads();
    }

    // epilogue
#pragma unroll
    for (int mt = 0; mt < 4; mt++) {
        int r0 = rowBase + wm * 64 + mt * 16 + g;
#pragma unroll
        for (int nt = 0; nt < 8; nt++) {
            int c = colBase + wn * 64 + nt * 8 + 2 * t4;
            float b0 = bias ? bias[c] : 0.f;
            float b1 = bias ? bias[c + 1] : 0.f;
            float v0 = acc[mt][nt][0] + b0, v1 = acc[mt][nt][1] + b1;
            float v2 = acc[mt][nt][2] + b0, v3 = acc[mt][nt][3] + b1;
            if (relu) {
                v0 = fmaxf(v0, 0.f); v1 = fmaxf(v1, 0.f);
                v2 = fmaxf(v2, 0.f); v3 = fmaxf(v3, 0.f);
            }
            *(float2*)(C + (size_t)r0 * N + c) = make_float2(v0, v1);
            *(float2*)(C + (size_t)(r0 + 8) * N + c) = make_float2(v2, v3);
        }
    }
}

// ---------------- fused attention: scores -> softmax -> write P -> P@V ----------------
// qkv layout: [b*S+s][1536], q at col h*64, k at 512+h*64, v at 1024+h*64.
__global__ void __launch_bounds__(256) attention_kernel(
    const float* __restrict__ qkv, const int* __restrict__ nkeep,
    float* __restrict__ attns, float* __restrict__ heads) {
    extern __shared__ float smd[];
    float* Ss = smd;                 // 32*512
    float* Ks = smd + 32 * 512;      // 64*65 (reused for V)
    float* Qs = Ks + 64 * 65;        // 32*65
    int bh = blockIdx.x;
    int b = bh >> 3, h = bh & 7;
    int s0 = blockIdx.y * 32;
    int tid = threadIdx.x;
    int nk = nkeep[b];
    const float inv_temp = 0.04419417382415922f;  // 1/sqrt(512)
    const int QSTR = 3 * DM;

    for (int i = tid; i < 32 * 64; i += 256) {
        int r = i >> 6, kk = i & 63;
        Qs[r * 65 + kk] = qkv[((size_t)(b * SS + s0 + r)) * QSTR + h * 64 + kk];
    }
    int r = tid >> 3, cg = tid & 7;

    for (int t0 = 0; t0 < SS; t0 += 64) {
        __syncthreads();
        for (int i = tid; i < 64 * 64; i += 256) {
            int tt = i >> 6, kk = i & 63;
            Ks[tt * 65 + kk] = qkv[((size_t)(b * SS + t0 + tt)) * QSTR + 512 + h * 64 + kk];
        }
        __syncthreads();
        float acc[8];
#pragma unroll
        for (int j = 0; j < 8; j++) acc[j] = 0.f;
#pragma unroll
        for (int kk = 0; kk < 64; kk++) {
            float a = Qs[r * 65 + kk];
#pragma unroll
            for (int j = 0; j < 8; j++) acc[j] += a * Ks[(cg * 8 + j) * 65 + kk];
        }
#pragma unroll
        for (int j = 0; j < 8; j++) {
            int t = t0 + cg * 8 + j;
            Ss[r * 512 + t] = (t < nk) ? acc[j] * inv_temp : -INFINITY;
        }
    }
    __syncthreads();

    // softmax: 8 threads per row; thread owns 64 contiguous cols
    {
        float m = -INFINITY;
        for (int i = 0; i < 64; i++) m = fmaxf(m, Ss[r * 512 + cg * 64 + i]);
        for (int o = 1; o < 8; o <<= 1) m = fmaxf(m, __shfl_xor_sync(~0u, m, o));
        float sum = 0.f;
        for (int i = 0; i < 64; i++) {
            float e = __expf(Ss[r * 512 + cg * 64 + i] - m);
            Ss[r * 512 + cg * 64 + i] = e;
            sum += e;
        }
        for (int o = 1; o < 8; o <<= 1) sum += __shfl_xor_sync(~0u, sum, o);
        float inv = 1.f / sum;
        for (int i = 0; i < 64; i++) Ss[r * 512 + cg * 64 + i] *= inv;
    }
    __syncthreads();

    // write P to attns region: index [h*B + b][s][t]
    {
        float* dst = attns + (((size_t)(h * BB + b)) * SS + s0) * SS;
        for (int i = tid; i < 32 * 512; i += 256) dst[i] = Ss[i];
    }

    // O = P @ V
    float o[8];
#pragma unroll
    for (int j = 0; j < 8; j++) o[j] = 0.f;
    for (int t0 = 0; t0 < SS; t0 += 64) {
        __syncthreads();
        for (int i = tid; i < 64 * 64; i += 256) {
            int tt = i >> 6, vv = i & 63;
            Ks[tt * 65 + vv] = qkv[((size_t)(b * SS + t0 + tt)) * QSTR + 1024 + h * 64 + vv];
        }
        __syncthreads();
#pragma unroll
        for (int tt = 0; tt < 64; tt++) {
            float p = Ss[r * 512 + t0 + tt];
#pragma unroll
            for (int j = 0; j < 8; j++) o[j] += p * Ks[tt * 65 + cg * 8 + j];
        }
    }
#pragma unroll
    for (int j = 0; j < 8; j++)
        heads[((size_t)(b * SS + s0 + r)) * DM + h * 64 + cg * 8 + j] = o[j];
}

// ---------------- layernorm (unbiased var, eps added to std) with residual ----------------
__global__ void ln_kernel(const float* __restrict__ y, const float* __restrict__ resid,
                          const float* __restrict__ g, const float* __restrict__ be,
                          float* __restrict__ out) {
    int row = blockIdx.x;
    int tid = threadIdx.x;  // 128
    float4 a = ((const float4*)(y + (size_t)row * DM))[tid];
    float4 b = ((const float4*)(resid + (size_t)row * DM))[tid];
    float v0 = a.x + b.x, v1 = a.y + b.y, v2 = a.z + b.z, v3 = a.w + b.w;
    float s = v0 + v1 + v2 + v3;
    float ss = v0 * v0 + v1 * v1 + v2 * v2 + v3 * v3;
    for (int o = 16; o; o >>= 1) {
        s += __shfl_xor_sync(~0u, s, o);
        ss += __shfl_xor_sync(~0u, ss, o);
    }
    __shared__ float shs[4], shss[4];
    int w = tid >> 5, l = tid & 31;
    if (l == 0) { shs[w] = s; shss[w] = ss; }
    __syncthreads();
    s = shs[0] + shs[1] + shs[2] + shs[3];
    ss = shss[0] + shss[1] + shss[2] + shss[3];
    float mu = s * (1.f / 512.f);
    float var = fmaxf((ss - 512.f * mu * mu) * (1.f / 511.f), 0.f);
    float inv = 1.f / (sqrtf(var) + EPSLN);
    float4 gg = ((const float4*)g)[tid];
    float4 bb = ((const float4*)be)[tid];
    float4 o;
    o.x = (v0 - mu) * inv * gg.x + bb.x;
    o.y = (v1 - mu) * inv * gg.y + bb.y;
    o.z = (v2 - mu) * inv * gg.z + bb.z;
    o.w = (v3 - mu) * inv * gg.w + bb.w;
    ((float4*)(out + (size_t)row * DM))[tid] = o;
}

// ---------------- launch ----------------
extern "C" void kernel_launch(void* const* d_in, const int* in_sizes, int n_in,
                              void* d_out, int out_size) {
    const float* x      = (const float*)d_in[0];
    const float* w_qs   = (const float*)d_in[1];
    const float* w_ks   = (const float*)d_in[2];
    const float* w_vs   = (const float*)d_in[3];
    const float* proj_w = (const float*)d_in[4];
    const float* proj_b = (const float*)d_in[5];
    const float* ln1_g  = (const float*)d_in[6];
    const float* ln1_b  = (const float*)d_in[7];
    const float* ffn_w1 = (const float*)d_in[8];
    const float* ffn_b1 = (const float*)d_in[9];
    const float* ffn_w2 = (const float*)d_in[10];
    const float* ffn_b2 = (const float*)d_in[11];
    const float* ln2_g  = (const float*)d_in[12];
    const float* ln2_b  = (const float*)d_in[13];
    const int*   keepm  = (const int*)d_in[14];

    float* out = (float*)d_out;
    float* enc_out = out;                 // [B,S,D]
    float* attns   = out + ENC_ELEMS;     // [H*B,S,S]

    float *xc, *qkv, *heads, *tmp, *attn_out, *ffnh, *wqkv;
    int *idx, *nk;
    cudaGetSymbolAddress((void**)&xc, g_xc);
    cudaGetSymbolAddress((void**)&qkv, g_qkv);
    cudaGetSymbolAddress((void**)&heads, g_heads);
    cudaGetSymbolAddress((void**)&tmp, g_tmp);
    cudaGetSymbolAddress((void**)&attn_out, g_attnout);
    cudaGetSymbolAddress((void**)&ffnh, g_ffnh);
    cudaGetSymbolAddress((void**)&wqkv, g_wqkv);
    cudaGetSymbolAddress((void**)&idx, g_idx);
    cudaGetSymbolAddress((void**)&nk, g_nkeep);

    static int smem_set = 0;
    if (!smem_set) {
        cudaFuncSetAttribute(attention_kernel, cudaFuncAttributeMaxDynamicSharedMemorySize,
                             (32 * 512 + 64 * 65 + 32 * 65) * 4);
        cudaFuncSetAttribute(tc_gemm, cudaFuncAttributeMaxDynamicSharedMemorySize,
                             GSMEM_FLOATS * 4);
        smem_set = 1;
    }
    const int gemm_smem = GSMEM_FLOATS * 4;
    const int att_smem = (32 * 512 + 64 * 65 + 32 * 65) * 4;

    // 1. skipper
    skipper_scan<<<BB, SS>>>(keepm, idx, nk);
    gather_kernel<<<MTOT, 128>>>(x, idx, nk, xc);

    // 2. pack QKV weights
    pack_wqkv<<<(DM * DM) / 256, 256>>>(w_qs, w_ks, w_vs, wqkv);

    // 3. fused QKV projection: [16384,512] @ [512,1536]
    tc_gemm<<<dim3(1536 / GBN, MTOT / GBM), 256, gemm_smem>>>(
        xc, wqkv, qkv, MTOT, 1536, DM, nullptr, 0);

    // 4. fused attention (writes attns + heads)
    attention_kernel<<<dim3(BB * NH, SS / 32), 256, att_smem>>>(qkv, nk, attns, heads);

    // 5. output projection + LN1
    tc_gemm<<<dim3(DM / GBN, MTOT / GBM), 256, gemm_smem>>>(
        heads, proj_w, tmp, MTOT, DM, DM, proj_b, 0);
    ln_kernel<<<MTOT, 128>>>(tmp, xc, ln1_g, ln1_b, attn_out);

    // 6. FFN
    tc_gemm<<<dim3(DINNER / GBN, MTOT / GBM), 256, gemm_smem>>>(
        attn_out, ffn_w1, ffnh, MTOT, DINNER, DM, ffn_b1, 1);
    tc_gemm<<<dim3(DM / GBN, MTOT / GBM), 256, gemm_smem>>>(
        ffnh, ffn_w2, tmp, MTOT, DM, DINNER, ffn_b2, 0);
    ln_kernel<<<MTOT, 128>>>(tmp, attn_out, ln2_g, ln2_b, enc_out);
}

// round 4
// speedup vs baseline: 3.8324x; 2.5918x over previous
#include <cuda_runtime.h>
#include <math.h>
#include <stdint.h>

// ---------------- problem constants ----------------
#define BB 32
#define SS 512
#define DM 512
#define NH 8
#define DK 64
#define DINNER 2048
#define MTOT (BB * SS)              // 16384 rows
#define ENC_ELEMS (BB * SS * DM)    // 8388608
#define EPSLN 1e-3f

// ---------------- scratch (device globals; no allocation allowed) ----------------
__device__ float g_xc[MTOT * DM];          // compacted input
__device__ float g_qkv[MTOT * 3 * DM];     // merged q|k|v  [row][1536]
__device__ float g_heads[MTOT * DM];       // attn heads concat
__device__ float g_tmp[MTOT * DM];         // pre-LN gemm out (reused)
__device__ float g_attnout[MTOT * DM];     // LN1 output
__device__ float g_ffnh[MTOT * DINNER];    // FFN hidden
__device__ float g_wqkv[DM * 3 * DM];      // packed [d][1536]
__device__ int   g_idx[BB * SS];
__device__ int   g_nkeep[BB];

// ---------------- small helpers ----------------
__device__ __forceinline__ uint32_t f2tf32(float f) {
    uint32_t u;
    asm("cvt.rna.tf32.f32 %0, %1;" : "=r"(u) : "f"(f));
    return u;
}
__device__ __forceinline__ void cpa16(uint32_t dst, const float* src) {
    asm volatile("cp.async.cg.shared.global [%0], [%1], 16;" :: "r"(dst), "l"(src));
}
__device__ __forceinline__ void mma_tf32(float* d, const uint32_t* a, const uint32_t* b) {
    asm volatile(
        "mma.sync.aligned.m16n8k8.row.col.f32.tf32.tf32.f32 "
        "{%0,%1,%2,%3}, {%4,%5,%6,%7}, {%8,%9}, {%0,%1,%2,%3};"
        : "+f"(d[0]), "+f"(d[1]), "+f"(d[2]), "+f"(d[3])
        : "r"(a[0]), "r"(a[1]), "r"(a[2]), "r"(a[3]), "r"(b[0]), "r"(b[1]));
}
// fast exp via 2^t split + degree-5 poly (rel err ~3e-6, |x| < ~60)
__device__ __forceinline__ float fast_exp(float x) {
    float t = x * 1.4426950408889634f;
    float z = t + 12582912.0f;
    int   m = __float_as_int(z) - 0x4B400000;
    float f = t - (z - 12582912.0f);
    float p = 1.3333558146e-3f;
    p = fmaf(p, f, 9.6181291076e-3f);
    p = fmaf(p, f, 5.5504108665e-2f);
    p = fmaf(p, f, 2.4022650696e-1f);
    p = fmaf(p, f, 6.9314718056e-1f);
    p = fmaf(p, f, 1.0f);
    return __int_as_float(__float_as_int(p) + (m << 23));
}

// ---------------- skipper: stable compaction scan ----------------
__global__ void skipper_scan(const int* __restrict__ keep, int* __restrict__ idx,
                             int* __restrict__ nkeep) {
    int b = blockIdx.x, t = threadIdx.x;  // 512 threads
    __shared__ int sh[SS];
    int v = keep[b * SS + t] > 0;
    sh[t] = v;
    __syncthreads();
    for (int off = 1; off < SS; off <<= 1) {
        int x = (t >= off) ? sh[t - off] : 0;
        __syncthreads();
        sh[t] += x;
        __syncthreads();
    }
    int incl = sh[t];
    if (v) idx[b * SS + incl - 1] = t;
    if (t == SS - 1) nkeep[b] = incl;
}

__global__ void gather_kernel(const float* __restrict__ x, const int* __restrict__ idx,
                              const int* __restrict__ nkeep, float* __restrict__ xc) {
    int bs = blockIdx.x;
    int b = bs >> 9, s = bs & 511;
    int nk = nkeep[b];
    float4* o = (float4*)(xc + (size_t)bs * DM);
    if (s < nk) {
        const float4* src = (const float4*)(x + ((size_t)b * SS + idx[b * SS + s]) * DM);
        o[threadIdx.x] = src[threadIdx.x];
    } else {
        o[threadIdx.x] = make_float4(0.f, 0.f, 0.f, 0.f);
    }
}

__global__ void pack_wqkv(const float* __restrict__ wq, const float* __restrict__ wk,
                          const float* __restrict__ wv, float* __restrict__ wp) {
    int i = blockIdx.x * 256 + threadIdx.x;  // over 512*512
    int d = i >> 9;
    int n = i & 511;
    int h = n >> 6, kk = n & 63;
    int src = (h * DM + d) * DK + kk;
    wp[(size_t)d * 1536 + n]        = wq[src];
    wp[(size_t)d * 1536 + 512 + n]  = wk[src];
    wp[(size_t)d * 1536 + 1024 + n] = wv[src];
}

// ---------------- tf32 tensor-core GEMM, 128x128 tile, 2 CTA/SM ----------------
#define GBM 128
#define GBN 128
#define GBK 16
#define ASTR 20     // 20 % 32 = 20 -> conflict-free A-fragment pattern
#define BSTR 136    // 136 % 32 = 8 -> conflict-free B-fragment pattern
#define AS_ELEMS (GBM * ASTR)        // 2560
#define BS_ELEMS (GBK * BSTR)        // 2176
#define GSMEM_FLOATS (2 * (AS_ELEMS + BS_ELEMS))  // 9472 -> 37888 B

__global__ void __launch_bounds__(256, 2) tc_gemm(
    const float* __restrict__ A, const float* __restrict__ B, float* __restrict__ C,
    int M, int N, int K, const float* __restrict__ bias, int relu) {
    extern __shared__ float sm[];
    float* As[2] = {sm, sm + AS_ELEMS};
    float* Bs[2] = {sm + 2 * AS_ELEMS, sm + 2 * AS_ELEMS + BS_ELEMS};
    uint32_t sbase = (uint32_t)__cvta_generic_to_shared(sm);

    int tid = threadIdx.x;
    int wid = tid >> 5, lane = tid & 31;
    int g = lane >> 2, t4 = lane & 3;
    int wm = wid >> 2, wn = wid & 3;          // 2 x 4 warp grid, warp tile 64x32
    int rowBase = blockIdx.y * GBM;
    int colBase = blockIdx.x * GBN;

    // global load coords
    int ar = tid >> 1;              // A row 0..127
    int ac4 = (tid & 1) * 4;        // cols {0,4} then +8
    int bkr = tid >> 5;             // B k-row 0..7 then +8
    int bn4 = (tid & 31) * 4;

    const float* Arow = A + (size_t)(rowBase + ar) * K + ac4;
    const float* Bb0 = B + (size_t)bkr * N + colBase + bn4;
    const float* Bb1 = B + (size_t)(bkr + 8) * N + colBase + bn4;

    float acc[4][4][4];
#pragma unroll
    for (int i = 0; i < 4; i++)
#pragma unroll
        for (int j = 0; j < 4; j++)
#pragma unroll
            for (int c = 0; c < 4; c++) acc[i][j][c] = 0.f;

    int nkt = K / GBK;
    // prologue
    {
        uint32_t ad = sbase + (ar * ASTR + ac4) * 4;
        cpa16(ad, Arow);
        cpa16(ad + 8 * 4, Arow + 8);
        uint32_t bd = sbase + (2 * AS_ELEMS + bkr * BSTR + bn4) * 4;
        cpa16(bd, Bb0);
        cpa16(bd + 8 * BSTR * 4, Bb1);
        asm volatile("cp.async.commit_group;");
    }

    for (int kt = 0; kt < nkt; kt++) {
        if (kt + 1 < nkt) {
            int buf = (kt + 1) & 1;
            int k0 = (kt + 1) * GBK;
            uint32_t ad = sbase + (buf * AS_ELEMS + ar * ASTR + ac4) * 4;
            cpa16(ad, Arow + k0);
            cpa16(ad + 8 * 4, Arow + k0 + 8);
            uint32_t bd = sbase + ((2 * AS_ELEMS + buf * BS_ELEMS) + bkr * BSTR + bn4) * 4;
            cpa16(bd, Bb0 + (size_t)k0 * N);
            cpa16(bd + 8 * BSTR * 4, Bb1 + (size_t)k0 * N);
            asm volatile("cp.async.commit_group;");
            asm volatile("cp.async.wait_group 1;");
        } else {
            asm volatile("cp.async.wait_group 0;");
        }
        __syncthreads();

        const float* as = As[kt & 1];
        const float* bs = Bs[kt & 1];
#pragma unroll
        for (int ks = 0; ks < 2; ks++) {
            int kk = ks * 8 + t4;
            uint32_t af[4][4];
#pragma unroll
            for (int mt = 0; mt < 4; mt++) {
                int m0 = wm * 64 + mt * 16;
                af[mt][0] = f2tf32(as[(m0 + g) * ASTR + kk]);
                af[mt][1] = f2tf32(as[(m0 + g + 8) * ASTR + kk]);
                af[mt][2] = f2tf32(as[(m0 + g) * ASTR + kk + 4]);
                af[mt][3] = f2tf32(as[(m0 + g + 8) * ASTR + kk + 4]);
            }
            uint32_t bf[4][2];
#pragma unroll
            for (int nt = 0; nt < 4; nt++) {
                int n0 = wn * 32 + nt * 8 + g;
                bf[nt][0] = f2tf32(bs[(ks * 8 + t4) * BSTR + n0]);
                bf[nt][1] = f2tf32(bs[(ks * 8 + t4 + 4) * BSTR + n0]);
            }
#pragma unroll
            for (int mt = 0; mt < 4; mt++)
#pragma unroll
                for (int nt = 0; nt < 4; nt++) mma_tf32(acc[mt][nt], af[mt], bf[nt]);
        }
        __syncthreads();
    }

    // epilogue
#pragma unroll
    for (int mt = 0; mt < 4; mt++) {
        int r0 = rowBase + wm * 64 + mt * 16 + g;
#pragma unroll
        for (int nt = 0; nt < 4; nt++) {
            int c = colBase + wn * 32 + nt * 8 + 2 * t4;
            float b0 = bias ? bias[c] : 0.f;
            float b1 = bias ? bias[c + 1] : 0.f;
            float v0 = acc[mt][nt][0] + b0, v1 = acc[mt][nt][1] + b1;
            float v2 = acc[mt][nt][2] + b0, v3 = acc[mt][nt][3] + b1;
            if (relu) {
                v0 = fmaxf(v0, 0.f); v1 = fmaxf(v1, 0.f);
                v2 = fmaxf(v2, 0.f); v3 = fmaxf(v3, 0.f);
            }
            *(float2*)(C + (size_t)r0 * N + c) = make_float2(v0, v1);
            *(float2*)(C + (size_t)(r0 + 8) * N + c) = make_float2(v2, v3);
        }
    }
}

// ---------------- tensor-core attention ----------------
// block = (b,h) x 64-row s-tile.  256 threads / 8 warps.
// smem: Qs[64][68], KV[128][72] (K uses stride 68, V stride 72), Es[64][516], rinv[64]
#define AQSTR 68
#define AKSTR 68
#define AVSTR 72
#define AESTR 516
#define ATT_SMEM_FLOATS (64 * AQSTR + 128 * AVSTR + 64 * AESTR + 64)

__global__ void __launch_bounds__(256, 1) attention_tc(
    const float* __restrict__ qkv, const int* __restrict__ nkeep,
    float* __restrict__ attns, float* __restrict__ heads) {
    extern __shared__ float sm[];
    float* Qs = sm;                       // 64 x 68
    float* KV = sm + 64 * AQSTR;          // 128 x 72 (union K/V)
    float* Es = KV + 128 * AVSTR;         // 64 x 516
    float* rinv = Es + 64 * AESTR;        // 64

    int bh = blockIdx.x;
    int b = bh >> 3, h = bh & 7;
    int s0 = blockIdx.y * 64;
    int tid = threadIdx.x;
    int wid = tid >> 5, lane = tid & 31;
    int g = lane >> 2, t4 = lane & 3;
    int nk = nkeep[b];
    const float sc = 0.04419417382415922f;  // 1/sqrt(512)
    const int QSTRIDE = 3 * DM;

    // load Q tile 64x64
    for (int i = tid; i < 1024; i += 256) {
        int row = i >> 4, c4 = (i & 15) * 4;
        float4 v = *(const float4*)(qkv + ((size_t)(b * SS + s0 + row)) * QSTRIDE + h * 64 + c4);
        *(float4*)&Qs[row * AQSTR + c4] = v;
    }

    // ---- Phase A: S = Q K^T, exp'd into Es ----
    int wmA = wid >> 2, wnA = wid & 3;   // 2 x 4; warp tile m32 x n32 of the 64x128 chunk
    for (int t0 = 0; t0 < SS; t0 += 128) {
        __syncthreads();
        for (int i = tid; i < 2048; i += 256) {
            int row = i >> 4, c4 = (i & 15) * 4;
            float4 v = *(const float4*)(qkv + ((size_t)(b * SS + t0 + row)) * QSTRIDE + 512 + h * 64 + c4);
            *(float4*)&KV[row * AKSTR + c4] = v;
        }
        __syncthreads();

        float acc[2][4][4];
#pragma unroll
        for (int i = 0; i < 2; i++)
#pragma unroll
            for (int j = 0; j < 4; j++)
#pragma unroll
                for (int c = 0; c < 4; c++) acc[i][j][c] = 0.f;

#pragma unroll
        for (int k8 = 0; k8 < 8; k8++) {
            int kk = k8 * 8 + t4;
            uint32_t af[2][4];
#pragma unroll
            for (int mt = 0; mt < 2; mt++) {
                int m0 = wmA * 32 + mt * 16;
                af[mt][0] = f2tf32(Qs[(m0 + g) * AQSTR + kk]);
                af[mt][1] = f2tf32(Qs[(m0 + g + 8) * AQSTR + kk]);
                af[mt][2] = f2tf32(Qs[(m0 + g) * AQSTR + kk + 4]);
                af[mt][3] = f2tf32(Qs[(m0 + g + 8) * AQSTR + kk + 4]);
            }
            uint32_t bf[4][2];
#pragma unroll
            for (int nt = 0; nt < 4; nt++) {
                int n0 = wnA * 32 + nt * 8 + g;      // key index within chunk
                bf[nt][0] = f2tf32(KV[n0 * AKSTR + kk]);
                bf[nt][1] = f2tf32(KV[n0 * AKSTR + kk + 4]);
            }
#pragma unroll
            for (int mt = 0; mt < 2; mt++)
#pragma unroll
                for (int nt = 0; nt < 4; nt++) mma_tf32(acc[mt][nt], af[mt], bf[nt]);
        }

        // exp + mask + store
#pragma unroll
        for (int mt = 0; mt < 2; mt++) {
            int r0 = wmA * 32 + mt * 16 + g;
#pragma unroll
            for (int nt = 0; nt < 4; nt++) {
                int col = t0 + wnA * 32 + nt * 8 + 2 * t4;
                float e0 = (col     < nk) ? fast_exp(acc[mt][nt][0] * sc) : 0.f;
                float e1 = (col + 1 < nk) ? fast_exp(acc[mt][nt][1] * sc) : 0.f;
                float e2 = (col     < nk) ? fast_exp(acc[mt][nt][2] * sc) : 0.f;
                float e3 = (col + 1 < nk) ? fast_exp(acc[mt][nt][3] * sc) : 0.f;
                Es[r0 * AESTR + col] = e0;
                Es[r0 * AESTR + col + 1] = e1;
                Es[(r0 + 8) * AESTR + col] = e2;
                Es[(r0 + 8) * AESTR + col + 1] = e3;
            }
        }
    }
    __syncthreads();

    // ---- row sums -> rinv ----
    {
        int r = tid >> 2, q = tid & 3;
        const float* base = &Es[r * AESTR + q * 128];
        float sx = 0.f, sy = 0.f, sz = 0.f, sw = 0.f;
#pragma unroll
        for (int j = 0; j < 32; j++) {
            float4 v = *(const float4*)(base + j * 4);
            sx += v.x; sy += v.y; sz += v.z; sw += v.w;
        }
        float s = (sx + sy) + (sz + sw);
        s += __shfl_xor_sync(~0u, s, 1);
        s += __shfl_xor_sync(~0u, s, 2);
        if (q == 0) rinv[r] = 1.f / s;
    }
    __syncthreads();

    // ---- write normalized P to attns ----
    {
        float* dst = attns + (((size_t)(h * BB + b)) * SS + s0) * SS;
        for (int i = tid; i < 8192; i += 256) {
            int row = i >> 7, c4 = (i & 127) * 4;
            float4 v = *(const float4*)&Es[row * AESTR + c4];
            float riv = rinv[row];
            v.x *= riv; v.y *= riv; v.z *= riv; v.w *= riv;
            *(float4*)(dst + (size_t)row * SS + c4) = v;
        }
    }

    // ---- Phase B: O = (Es V) * rinv ----
    int wmB = wid >> 1, wnB = wid & 1;    // 4 x 2; warp tile m16 x n32
    float oacc[4][4];
#pragma unroll
    for (int j = 0; j < 4; j++)
#pragma unroll
        for (int c = 0; c < 4; c++) oacc[j][c] = 0.f;

    for (int t0 = 0; t0 < SS; t0 += 128) {
        __syncthreads();
        for (int i = tid; i < 2048; i += 256) {
            int row = i >> 4, c4 = (i & 15) * 4;
            float4 v = *(const float4*)(qkv + ((size_t)(b * SS + t0 + row)) * QSTRIDE + 1024 + h * 64 + c4);
            *(float4*)&KV[row * AVSTR + c4] = v;
        }
        __syncthreads();

        int m0 = wmB * 16;
#pragma unroll
        for (int k8 = 0; k8 < 16; k8++) {
            int kcol = t0 + k8 * 8 + t4;
            uint32_t af[4];
            af[0] = f2tf32(Es[(m0 + g) * AESTR + kcol]);
            af[1] = f2tf32(Es[(m0 + g + 8) * AESTR + kcol]);
            af[2] = f2tf32(Es[(m0 + g) * AESTR + kcol + 4]);
            af[3] = f2tf32(Es[(m0 + g + 8) * AESTR + kcol + 4]);
            uint32_t bfv[4][2];
#pragma unroll
            for (int nt = 0; nt < 4; nt++) {
                int n0 = wnB * 32 + nt * 8 + g;
                bfv[nt][0] = f2tf32(KV[(k8 * 8 + t4) * AVSTR + n0]);
                bfv[nt][1] = f2tf32(KV[(k8 * 8 + t4 + 4) * AVSTR + n0]);
            }
#pragma unroll
            for (int nt = 0; nt < 4; nt++) mma_tf32(oacc[nt], af, bfv[nt]);
        }
    }

    // write O
    {
        int r0 = wmB * 16 + g;
        float ri0 = rinv[r0], ri1 = rinv[r0 + 8];
        size_t base0 = ((size_t)(b * SS + s0 + r0)) * DM + h * 64;
        size_t base1 = ((size_t)(b * SS + s0 + r0 + 8)) * DM + h * 64;
#pragma unroll
        for (int nt = 0; nt < 4; nt++) {
            int c = wnB * 32 + nt * 8 + 2 * t4;
            *(float2*)(heads + base0 + c) = make_float2(oacc[nt][0] * ri0, oacc[nt][1] * ri0);
            *(float2*)(heads + base1 + c) = make_float2(oacc[nt][2] * ri1, oacc[nt][3] * ri1);
        }
    }
}

// ---------------- layernorm (unbiased var, eps added to std) with residual ----------------
__global__ void ln_kernel(const float* __restrict__ y, const float* __restrict__ resid,
                          const float* __restrict__ g, const float* __restrict__ be,
                          float* __restrict__ out) {
    int row = blockIdx.x;
    int tid = threadIdx.x;  // 128
    float4 a = ((const float4*)(y + (size_t)row * DM))[tid];
    float4 b = ((const float4*)(resid + (size_t)row * DM))[tid];
    float v0 = a.x + b.x, v1 = a.y + b.y, v2 = a.z + b.z, v3 = a.w + b.w;
    float s = v0 + v1 + v2 + v3;
    float ss = v0 * v0 + v1 * v1 + v2 * v2 + v3 * v3;
    for (int o = 16; o; o >>= 1) {
        s += __shfl_xor_sync(~0u, s, o);
        ss += __shfl_xor_sync(~0u, ss, o);
    }
    __shared__ float shs[4], shss[4];
    int w = tid >> 5, l = tid & 31;
    if (l == 0) { shs[w] = s; shss[w] = ss; }
    __syncthreads();
    s = shs[0] + shs[1] + shs[2] + shs[3];
    ss = shss[0] + shss[1] + shss[2] + shss[3];
    float mu = s * (1.f / 512.f);
    float var = fmaxf((ss - 512.f * mu * mu) * (1.f / 511.f), 0.f);
    float inv = 1.f / (sqrtf(var) + EPSLN);
    float4 gg = ((const float4*)g)[tid];
    float4 bb = ((const float4*)be)[tid];
    float4 o;
    o.x = (v0 - mu) * inv * gg.x + bb.x;
    o.y = (v1 - mu) * inv * gg.y + bb.y;
    o.z = (v2 - mu) * inv * gg.z + bb.z;
    o.w = (v3 - mu) * inv * gg.w + bb.w;
    ((float4*)(out + (size_t)row * DM))[tid] = o;
}

// ---------------- launch ----------------
extern "C" void kernel_launch(void* const* d_in, const int* in_sizes, int n_in,
                              void* d_out, int out_size) {
    const float* x      = (const float*)d_in[0];
    const float* w_qs   = (const float*)d_in[1];
    const float* w_ks   = (const float*)d_in[2];
    const float* w_vs   = (const float*)d_in[3];
    const float* proj_w = (const float*)d_in[4];
    const float* proj_b = (const float*)d_in[5];
    const float* ln1_g  = (const float*)d_in[6];
    const float* ln1_b  = (const float*)d_in[7];
    const float* ffn_w1 = (const float*)d_in[8];
    const float* ffn_b1 = (const float*)d_in[9];
    const float* ffn_w2 = (const float*)d_in[10];
    const float* ffn_b2 = (const float*)d_in[11];
    const float* ln2_g  = (const float*)d_in[12];
    const float* ln2_b  = (const float*)d_in[13];
    const int*   keepm  = (const int*)d_in[14];

    float* out = (float*)d_out;
    float* enc_out = out;                 // [B,S,D]
    float* attns   = out + ENC_ELEMS;     // [H*B,S,S]

    float *xc, *qkv, *heads, *tmp, *attn_out, *ffnh, *wqkv;
    int *idx, *nk;
    cudaGetSymbolAddress((void**)&xc, g_xc);
    cudaGetSymbolAddress((void**)&qkv, g_qkv);
    cudaGetSymbolAddress((void**)&heads, g_heads);
    cudaGetSymbolAddress((void**)&tmp, g_tmp);
    cudaGetSymbolAddress((void**)&attn_out, g_attnout);
    cudaGetSymbolAddress((void**)&ffnh, g_ffnh);
    cudaGetSymbolAddress((void**)&wqkv, g_wqkv);
    cudaGetSymbolAddress((void**)&idx, g_idx);
    cudaGetSymbolAddress((void**)&nk, g_nkeep);

    static int smem_set = 0;
    if (!smem_set) {
        cudaFuncSetAttribute(attention_tc, cudaFuncAttributeMaxDynamicSharedMemorySize,
                             ATT_SMEM_FLOATS * 4);
        cudaFuncSetAttribute(tc_gemm, cudaFuncAttributeMaxDynamicSharedMemorySize,
                             GSMEM_FLOATS * 4);
        smem_set = 1;
    }
    const int gemm_smem = GSMEM_FLOATS * 4;
    const int att_smem = ATT_SMEM_FLOATS * 4;

    // 1. skipper
    skipper_scan<<<BB, SS>>>(keepm, idx, nk);
    gather_kernel<<<MTOT, 128>>>(x, idx, nk, xc);

    // 2. pack QKV weights
    pack_wqkv<<<(DM * DM) / 256, 256>>>(w_qs, w_ks, w_vs, wqkv);

    // 3. fused QKV projection: [16384,512] @ [512,1536]
    tc_gemm<<<dim3(1536 / GBN, MTOT / GBM), 256, gemm_smem>>>(
        xc, wqkv, qkv, MTOT, 1536, DM, nullptr, 0);

    // 4. tensor-core attention (writes attns + heads)
    attention_tc<<<dim3(BB * NH, SS / 64), 256, att_smem>>>(qkv, nk, attns, heads);

    // 5. output projection + LN1
    tc_gemm<<<dim3(DM / GBN, MTOT / GBM), 256, gemm_smem>>>(
        heads, proj_w, tmp, MTOT, DM, DM, proj_b, 0);
    ln_kernel<<<MTOT, 128>>>(tmp, xc, ln1_g, ln1_b, attn_out);

    // 6. FFN
    tc_gemm<<<dim3(DINNER / GBN, MTOT / GBM), 256, gemm_smem>>>(
        attn_out, ffn_w1, ffnh, MTOT, DINNER, DM, ffn_b1, 1);
    tc_gemm<<<dim3(DM / GBN, MTOT / GBM), 256, gemm_smem>>>(
        ffnh, ffn_w2, tmp, MTOT, DM, DINNER, ffn_b2, 0);
    ln_kernel<<<MTOT, 128>>>(tmp, attn_out, ln2_g, ln2_b, enc_out);
}

// round 6
// speedup vs baseline: 6.4372x; 1.6797x over previous
#include <cuda_runtime.h>
#include <cuda_fp16.h>
#include <math.h>
#include <stdint.h>

// ---------------- problem constants ----------------
#define BB 32
#define SS 512
#define DM 512
#define NH 8
#define DK 64
#define DINNER 2048
#define MTOT (BB * SS)              // 16384 rows
#define ENC_ELEMS (BB * SS * DM)    // 8388608
#define EPSLN 1e-3f

// ---------------- scratch (device globals; no allocation allowed) ----------------
__device__ float  g_xc[MTOT * DM];          // compacted input (fp32 residual)
__device__ __half g_xch[MTOT * DM];         // fp16 copy (GEMM A)
__device__ float  g_qkv[MTOT * 3 * DM];     // merged q|k|v  [row][1536] fp32
__device__ __half g_headsh[MTOT * DM];      // attn heads (fp16)
__device__ float  g_tmp[MTOT * DM];         // pre-LN gemm out
__device__ float  g_attnout[MTOT * DM];     // LN1 output (fp32 residual)
__device__ __half g_attnouth[MTOT * DM];    // LN1 output (fp16)
__device__ __half g_ffnh[MTOT * DINNER];    // FFN hidden (fp16, relu'd)
__device__ __half g_wqkvT[1536 * DM];       // [n][k] fp16
__device__ __half g_projwT[DM * DM];
__device__ __half g_w1T[DINNER * DM];
__device__ __half g_w2T[DM * DINNER];
__device__ int    g_idx[BB * SS];
__device__ int    g_nkeep[BB];

// ---------------- helpers ----------------
__device__ __forceinline__ uint32_t f2tf32(float f) {
    uint32_t u;
    asm("cvt.rna.tf32.f32 %0, %1;" : "=r"(u) : "f"(f));
    return u;
}
__device__ __forceinline__ void cpa16(uint32_t dst, const void* src) {
    asm volatile("cp.async.cg.shared.global [%0], [%1], 16;" :: "r"(dst), "l"(src));
}
__device__ __forceinline__ void ldm_x4(uint32_t* r, uint32_t addr) {
    asm volatile("ldmatrix.sync.aligned.m8n8.x4.shared.b16 {%0,%1,%2,%3}, [%4];"
                 : "=r"(r[0]), "=r"(r[1]), "=r"(r[2]), "=r"(r[3]) : "r"(addr));
}
__device__ __forceinline__ void mma_f16(float* d, const uint32_t* a, uint32_t b0, uint32_t b1) {
    asm volatile(
        "mma.sync.aligned.m16n8k16.row.col.f32.f16.f16.f32 "
        "{%0,%1,%2,%3}, {%4,%5,%6,%7}, {%8,%9}, {%0,%1,%2,%3};"
        : "+f"(d[0]), "+f"(d[1]), "+f"(d[2]), "+f"(d[3])
        : "r"(a[0]), "r"(a[1]), "r"(a[2]), "r"(a[3]), "r"(b0), "r"(b1));
}
__device__ __forceinline__ void mma_tf32(float* d, const uint32_t* a, const uint32_t* b) {
    asm volatile(
        "mma.sync.aligned.m16n8k8.row.col.f32.tf32.tf32.f32 "
        "{%0,%1,%2,%3}, {%4,%5,%6,%7}, {%8,%9}, {%0,%1,%2,%3};"
        : "+f"(d[0]), "+f"(d[1]), "+f"(d[2]), "+f"(d[3])
        : "r"(a[0]), "r"(a[1]), "r"(a[2]), "r"(a[3]), "r"(b[0]), "r"(b[1]));
}
__device__ __forceinline__ float fast_exp(float x) {
    float t = x * 1.4426950408889634f;
    float z = t + 12582912.0f;
    int   m = __float_as_int(z) - 0x4B400000;
    float f = t - (z - 12582912.0f);
    float p = 1.3333558146e-3f;
    p = fmaf(p, f, 9.6181291076e-3f);
    p = fmaf(p, f, 5.5504108665e-2f);
    p = fmaf(p, f, 2.4022650696e-1f);
    p = fmaf(p, f, 6.9314718056e-1f);
    p = fmaf(p, f, 1.0f);
    return __int_as_float(__float_as_int(p) + (m << 23));
}
__device__ __forceinline__ uint32_t smem_u32(const void* p) {
    uint32_t a;
    asm("{ .reg .u64 t; cvta.to.shared.u64 t, %1; cvt.u32.u64 %0, t; }" : "=r"(a) : "l"(p));
    return a;
}

// ---------------- skipper ----------------
__global__ void skipper_scan(const int* __restrict__ keep, int* __restrict__ idx,
                             int* __restrict__ nkeep) {
    int b = blockIdx.x, t = threadIdx.x;
    __shared__ int sh[SS];
    int v = keep[b * SS + t] > 0;
    sh[t] = v;
    __syncthreads();
    for (int off = 1; off < SS; off <<= 1) {
        int x = (t >= off) ? sh[t - off] : 0;
        __syncthreads();
        sh[t] += x;
        __syncthreads();
    }
    int incl = sh[t];
    if (v) idx[b * SS + incl - 1] = t;
    if (t == SS - 1) nkeep[b] = incl;
}

__global__ void gather_kernel(const float* __restrict__ x, const int* __restrict__ idx,
                              const int* __restrict__ nkeep, float* __restrict__ xc,
                              __half* __restrict__ xch) {
    int bs = blockIdx.x;
    int b = bs >> 9, s = bs & 511;
    int nk = nkeep[b];
    float4 v = make_float4(0.f, 0.f, 0.f, 0.f);
    if (s < nk)
        v = ((const float4*)(x + ((size_t)b * SS + idx[b * SS + s]) * DM))[threadIdx.x];
    ((float4*)(xc + (size_t)bs * DM))[threadIdx.x] = v;
    __half2 h0 = __floats2half2_rn(v.x, v.y);
    __half2 h1 = __floats2half2_rn(v.z, v.w);
    uint2 u;
    u.x = *(uint32_t*)&h0;
    u.y = *(uint32_t*)&h1;
    ((uint2*)(xch + (size_t)bs * DM))[threadIdx.x] = u;
}

// pack per-head weights [H, D, 64] x3 -> transposed [1536][512] fp16
__global__ void pack_wqkv_t(const float* __restrict__ wq, const float* __restrict__ wk,
                            const float* __restrict__ wv, __half* __restrict__ wp) {
    int i = blockIdx.x * 256 + threadIdx.x;  // over 1536*512
    int n = i >> 9;
    int d = i & 511;
    int sel = n >> 9;
    int nn = n & 511;
    int h = nn >> 6, kk = nn & 63;
    const float* w = (sel == 0) ? wq : (sel == 1) ? wk : wv;
    wp[i] = __float2half_rn(w[(h * DM + d) * DK + kk]);
}

// transpose [R][C] fp32 -> [C][R] fp16
__global__ void transpose_half(const float* __restrict__ in, __half* __restrict__ out,
                               int R, int C) {
    __shared__ float t[32][33];
    int c0 = blockIdx.x * 32, r0 = blockIdx.y * 32;
    int x = threadIdx.x, y = threadIdx.y;  // 32 x 8
#pragma unroll
    for (int j = 0; j < 32; j += 8)
        t[y + j][x] = in[(size_t)(r0 + y + j) * C + c0 + x];
    __syncthreads();
#pragma unroll
    for (int j = 0; j < 32; j += 8)
        out[(size_t)(c0 + y + j) * R + r0 + x] = __float2half_rn(t[x][y + j]);
}

// ---------------- fp16 tensor-core GEMM ----------------
// C[M,N] = A[M,K] @ Bt[N,K]^T.  128x128 block tile, BK=64 halves (128B rows).
// smem: A0 A1 B0 B1, each 16KB, XOR-swizzled (chunk ^= row&7).
// 8 warps, warp tile 64x32 (4 x m16, 4 x n8), ldmatrix.x4 fragments.
#define HSM_TOTAL 65536

__global__ void __launch_bounds__(256, 2) hgemm(
    const __half* __restrict__ A, const __half* __restrict__ Bt,
    float* __restrict__ Cf, __half* __restrict__ Ch,
    int M, int N, int K, const float* __restrict__ bias, int relu) {
    extern __shared__ __align__(128) char smc[];
    uint32_t sbase = smem_u32(smc);

    int tid = threadIdx.x;
    int wid = tid >> 5, lane = tid & 31;
    int g = lane >> 2, t4 = lane & 3;
    int l15 = lane & 15, l16 = lane >> 4;
    int wm = wid >> 2, wn = wid & 3;          // 2 x 4 warps, tile 64x32
    int rowBase = blockIdx.y * 128;
    int colBase = blockIdx.x * 128;

    float acc[4][4][4];
#pragma unroll
    for (int i = 0; i < 4; i++)
#pragma unroll
        for (int j = 0; j < 4; j++)
#pragma unroll
            for (int c = 0; c < 4; c++) acc[i][j][c] = 0.f;

    const int nc = K / 64;

    auto load_tile = [&](int kt, int buf) {
        int k0 = kt * 64;
#pragma unroll
        for (int j = 0; j < 4; j++) {
            int cid = tid + 256 * j;          // 0..1023
            int row = cid >> 3, c = cid & 7;
            uint32_t off = row * 128 + ((c ^ (row & 7)) << 4);
            cpa16(sbase + buf * 16384 + off,
                  A + (size_t)(rowBase + row) * K + k0 + c * 8);
            cpa16(sbase + 32768 + buf * 16384 + off,
                  Bt + (size_t)(colBase + row) * K + k0 + c * 8);
        }
        asm volatile("cp.async.commit_group;");
    };

    load_tile(0, 0);
    if (nc > 1) load_tile(1, 1);

    for (int kt = 0; kt < nc; kt++) {
        int buf = kt & 1;
        if (kt + 2 < nc) {
            asm volatile("cp.async.wait_group 1;");
        } else {
            asm volatile("cp.async.wait_group 0;");
        }
        __syncthreads();

        uint32_t aBase = sbase + buf * 16384;
        uint32_t bBase = sbase + 32768 + buf * 16384;
#pragma unroll
        for (int ks = 0; ks < 4; ks++) {
            int ch = 2 * ks + l16;
            uint32_t a[4][4];
#pragma unroll
            for (int mt = 0; mt < 4; mt++) {
                int row = wm * 64 + mt * 16 + l15;
                ldm_x4(a[mt], aBase + row * 128 + ((ch ^ (row & 7)) << 4));
            }
            uint32_t bq[2][4];
#pragma unroll
            for (int bt = 0; bt < 2; bt++) {
                int row = wn * 32 + bt * 16 + l15;
                ldm_x4(bq[bt], bBase + row * 128 + ((ch ^ (row & 7)) << 4));
            }
#pragma unroll
            for (int mt = 0; mt < 4; mt++)
#pragma unroll
                for (int nt = 0; nt < 4; nt++)
                    mma_f16(acc[mt][nt], a[mt], bq[nt >> 1][nt & 1], bq[nt >> 1][2 + (nt & 1)]);
        }
        __syncthreads();

        if (kt + 2 < nc) load_tile(kt + 2, buf);
    }

    // epilogue
#pragma unroll
    for (int mt = 0; mt < 4; mt++) {
        int r0 = rowBase + wm * 64 + mt * 16 + g;
#pragma unroll
        for (int nt = 0; nt < 4; nt++) {
            int c = colBase + wn * 32 + nt * 8 + 2 * t4;
            float b0 = bias ? __ldg(bias + c) : 0.f;
            float b1 = bias ? __ldg(bias + c + 1) : 0.f;
            float v0 = acc[mt][nt][0] + b0, v1 = acc[mt][nt][1] + b1;
            float v2 = acc[mt][nt][2] + b0, v3 = acc[mt][nt][3] + b1;
            if (relu) {
                v0 = fmaxf(v0, 0.f); v1 = fmaxf(v1, 0.f);
                v2 = fmaxf(v2, 0.f); v3 = fmaxf(v3, 0.f);
            }
            if (Cf) {
                *(float2*)(Cf + (size_t)r0 * N + c) = make_float2(v0, v1);
                *(float2*)(Cf + (size_t)(r0 + 8) * N + c) = make_float2(v2, v3);
            }
            if (Ch) {
                *(__half2*)(Ch + (size_t)r0 * N + c) = __floats2half2_rn(v0, v1);
                *(__half2*)(Ch + (size_t)(r0 + 8) * N + c) = __floats2half2_rn(v2, v3);
            }
        }
    }
}

// ---------------- tensor-core attention (tf32 mma.sync; heads out fp16) ----------------
#define AQSTR 68
#define AKSTR 68
#define AVSTR 72
#define AESTR 516
#define ATT_SMEM_FLOATS (64 * AQSTR + 128 * AVSTR + 64 * AESTR + 64)

__global__ void __launch_bounds__(256, 1) attention_tc(
    const float* __restrict__ qkv, const int* __restrict__ nkeep,
    float* __restrict__ attns, __half* __restrict__ heads) {
    extern __shared__ float sm[];
    float* Qs = sm;
    float* KV = sm + 64 * AQSTR;
    float* Es = KV + 128 * AVSTR;
    float* rinv = Es + 64 * AESTR;

    int bh = blockIdx.x;
    int b = bh >> 3, h = bh & 7;
    int s0 = blockIdx.y * 64;
    int tid = threadIdx.x;
    int wid = tid >> 5, lane = tid & 31;
    int g = lane >> 2, t4 = lane & 3;
    int nk = nkeep[b];
    const float sc = 0.04419417382415922f;
    const int QSTRIDE = 3 * DM;

    for (int i = tid; i < 1024; i += 256) {
        int row = i >> 4, c4 = (i & 15) * 4;
        float4 v = *(const float4*)(qkv + ((size_t)(b * SS + s0 + row)) * QSTRIDE + h * 64 + c4);
        *(float4*)&Qs[row * AQSTR + c4] = v;
    }

    int wmA = wid >> 2, wnA = wid & 3;
    for (int t0 = 0; t0 < SS; t0 += 128) {
        __syncthreads();
        for (int i = tid; i < 2048; i += 256) {
            int row = i >> 4, c4 = (i & 15) * 4;
            float4 v = *(const float4*)(qkv + ((size_t)(b * SS + t0 + row)) * QSTRIDE + 512 + h * 64 + c4);
            *(float4*)&KV[row * AKSTR + c4] = v;
        }
        __syncthreads();

        float acc[2][4][4];
#pragma unroll
        for (int i = 0; i < 2; i++)
#pragma unroll
            for (int j = 0; j < 4; j++)
#pragma unroll
                for (int c = 0; c < 4; c++) acc[i][j][c] = 0.f;

#pragma unroll
        for (int k8 = 0; k8 < 8; k8++) {
            int kk = k8 * 8 + t4;
            uint32_t af[2][4];
#pragma unroll
            for (int mt = 0; mt < 2; mt++) {
                int m0 = wmA * 32 + mt * 16;
                af[mt][0] = f2tf32(Qs[(m0 + g) * AQSTR + kk]);
                af[mt][1] = f2tf32(Qs[(m0 + g + 8) * AQSTR + kk]);
                af[mt][2] = f2tf32(Qs[(m0 + g) * AQSTR + kk + 4]);
                af[mt][3] = f2tf32(Qs[(m0 + g + 8) * AQSTR + kk + 4]);
            }
            uint32_t bf[4][2];
#pragma unroll
            for (int nt = 0; nt < 4; nt++) {
                int n0 = wnA * 32 + nt * 8 + g;
                bf[nt][0] = f2tf32(KV[n0 * AKSTR + kk]);
                bf[nt][1] = f2tf32(KV[n0 * AKSTR + kk + 4]);
            }
#pragma unroll
            for (int mt = 0; mt < 2; mt++)
#pragma unroll
                for (int nt = 0; nt < 4; nt++) mma_tf32(acc[mt][nt], af[mt], bf[nt]);
        }

#pragma unroll
        for (int mt = 0; mt < 2; mt++) {
            int r0 = wmA * 32 + mt * 16 + g;
#pragma unroll
            for (int nt = 0; nt < 4; nt++) {
                int col = t0 + wnA * 32 + nt * 8 + 2 * t4;
                float e0 = (col     < nk) ? fast_exp(acc[mt][nt][0] * sc) : 0.f;
                float e1 = (col + 1 < nk) ? fast_exp(acc[mt][nt][1] * sc) : 0.f;
                float e2 = (col     < nk) ? fast_exp(acc[mt][nt][2] * sc) : 0.f;
                float e3 = (col + 1 < nk) ? fast_exp(acc[mt][nt][3] * sc) : 0.f;
                Es[r0 * AESTR + col] = e0;
                Es[r0 * AESTR + col + 1] = e1;
                Es[(r0 + 8) * AESTR + col] = e2;
                Es[(r0 + 8) * AESTR + col + 1] = e3;
            }
        }
    }
    __syncthreads();

    {
        int r = tid >> 2, q = tid & 3;
        const float* base = &Es[r * AESTR + q * 128];
        float sx = 0.f, sy = 0.f, sz = 0.f, sw = 0.f;
#pragma unroll
        for (int j = 0; j < 32; j++) {
            float4 v = *(const float4*)(base + j * 4);
            sx += v.x; sy += v.y; sz += v.z; sw += v.w;
        }
        float s = (sx + sy) + (sz + sw);
        s += __shfl_xor_sync(~0u, s, 1);
        s += __shfl_xor_sync(~0u, s, 2);
        if (q == 0) rinv[r] = 1.f / s;
    }
    __syncthreads();

    {
        float* dst = attns + (((size_t)(h * BB + b)) * SS + s0) * SS;
        for (int i = tid; i < 8192; i += 256) {
            int row = i >> 7, c4 = (i & 127) * 4;
            float4 v = *(const float4*)&Es[row * AESTR + c4];
            float riv = rinv[row];
            v.x *= riv; v.y *= riv; v.z *= riv; v.w *= riv;
            *(float4*)(dst + (size_t)row * SS + c4) = v;
        }
    }

    int wmB = wid >> 1, wnB = wid & 1;
    float oacc[4][4];
#pragma unroll
    for (int j = 0; j < 4; j++)
#pragma unroll
        for (int c = 0; c < 4; c++) oacc[j][c] = 0.f;

    for (int t0 = 0; t0 < SS; t0 += 128) {
        __syncthreads();
        for (int i = tid; i < 2048; i += 256) {
            int row = i >> 4, c4 = (i & 15) * 4;
            float4 v = *(const float4*)(qkv + ((size_t)(b * SS + t0 + row)) * QSTRIDE + 1024 + h * 64 + c4);
            *(float4*)&KV[row * AVSTR + c4] = v;
        }
        __syncthreads();

        int m0 = wmB * 16;
#pragma unroll
        for (int k8 = 0; k8 < 16; k8++) {
            int kcol = t0 + k8 * 8 + t4;
            uint32_t af[4];
            af[0] = f2tf32(Es[(m0 + g) * AESTR + kcol]);
            af[1] = f2tf32(Es[(m0 + g + 8) * AESTR + kcol]);
            af[2] = f2tf32(Es[(m0 + g) * AESTR + kcol + 4]);
            af[3] = f2tf32(Es[(m0 + g + 8) * AESTR + kcol + 4]);
            uint32_t bfv[4][2];
#pragma unroll
            for (int nt = 0; nt < 4; nt++) {
                int n0 = wnB * 32 + nt * 8 + g;
                bfv[nt][0] = f2tf32(KV[(k8 * 8 + t4) * AVSTR + n0]);
                bfv[nt][1] = f2tf32(KV[(k8 * 8 + t4 + 4) * AVSTR + n0]);
            }
#pragma unroll
            for (int nt = 0; nt < 4; nt++) mma_tf32(oacc[nt], af, bfv[nt]);
        }
    }

    {
        int r0 = wmB * 16 + g;
        float ri0 = rinv[r0], ri1 = rinv[r0 + 8];
        size_t base0 = ((size_t)(b * SS + s0 + r0)) * DM + h * 64;
        size_t base1 = ((size_t)(b * SS + s0 + r0 + 8)) * DM + h * 64;
#pragma unroll
        for (int nt = 0; nt < 4; nt++) {
            int c = wnB * 32 + nt * 8 + 2 * t4;
            *(__half2*)(heads + base0 + c) =
                __floats2half2_rn(oacc[nt][0] * ri0, oacc[nt][1] * ri0);
            *(__half2*)(heads + base1 + c) =
                __floats2half2_rn(oacc[nt][2] * ri1, oacc[nt][3] * ri1);
        }
    }
}

// ---------------- layernorm with residual; optional fp16 side copy ----------------
__global__ void ln_kernel(const float* __restrict__ y, const float* __restrict__ resid,
                          const float* __restrict__ g, const float* __restrict__ be,
                          float* __restrict__ out, __half* __restrict__ out_h) {
    int row = blockIdx.x;
    int tid = threadIdx.x;  // 128
    float4 a = ((const float4*)(y + (size_t)row * DM))[tid];
    float4 b = ((const float4*)(resid + (size_t)row * DM))[tid];
    float v0 = a.x + b.x, v1 = a.y + b.y, v2 = a.z + b.z, v3 = a.w + b.w;
    float s = v0 + v1 + v2 + v3;
    float ss = v0 * v0 + v1 * v1 + v2 * v2 + v3 * v3;
    for (int o = 16; o; o >>= 1) {
        s += __shfl_xor_sync(~0u, s, o);
        ss += __shfl_xor_sync(~0u, ss, o);
    }
    __shared__ float shs[4], shss[4];
    int w = tid >> 5, l = tid & 31;
    if (l == 0) { shs[w] = s; shss[w] = ss; }
    __syncthreads();
    s = shs[0] + shs[1] + shs[2] + shs[3];
    ss = shss[0] + shss[1] + shss[2] + shss[3];
    float mu = s * (1.f / 512.f);
    float var = fmaxf((ss - 512.f * mu * mu) * (1.f / 511.f), 0.f);
    float inv = 1.f / (sqrtf(var) + EPSLN);
    float4 gg = ((const float4*)g)[tid];
    float4 bb = ((const float4*)be)[tid];
    float4 o;
    o.x = (v0 - mu) * inv * gg.x + bb.x;
    o.y = (v1 - mu) * inv * gg.y + bb.y;
    o.z = (v2 - mu) * inv * gg.z + bb.z;
    o.w = (v3 - mu) * inv * gg.w + bb.w;
    ((float4*)(out + (size_t)row * DM))[tid] = o;
    if (out_h) {
        __half2 h0 = __floats2half2_rn(o.x, o.y);
        __half2 h1 = __floats2half2_rn(o.z, o.w);
        uint2 u;
        u.x = *(uint32_t*)&h0;
        u.y = *(uint32_t*)&h1;
        ((uint2*)(out_h + (size_t)row * DM))[tid] = u;
    }
}

// ---------------- launch ----------------
extern "C" void kernel_launch(void* const* d_in, const int* in_sizes, int n_in,
                              void* d_out, int out_size) {
    const float* x      = (const float*)d_in[0];
    const float* w_qs   = (const float*)d_in[1];
    const float* w_ks   = (const float*)d_in[2];
    const float* w_vs   = (const float*)d_in[3];
    const float* proj_w = (const float*)d_in[4];
    const float* proj_b = (const float*)d_in[5];
    const float* ln1_g  = (const float*)d_in[6];
    const float* ln1_b  = (const float*)d_in[7];
    const float* ffn_w1 = (const float*)d_in[8];
    const float* ffn_b1 = (const float*)d_in[9];
    const float* ffn_w2 = (const float*)d_in[10];
    const float* ffn_b2 = (const float*)d_in[11];
    const float* ln2_g  = (const float*)d_in[12];
    const float* ln2_b  = (const float*)d_in[13];
    const int*   keepm  = (const int*)d_in[14];

    float* out = (float*)d_out;
    float* enc_out = out;
    float* attns   = out + ENC_ELEMS;

    float *xc, *qkv, *tmp, *attn_out;
    __half *xch, *headsh, *attnouth, *ffnh, *wqkvT, *projwT, *w1T, *w2T;
    int *idx, *nk;
    cudaGetSymbolAddress((void**)&xc, g_xc);
    cudaGetSymbolAddress((void**)&xch, g_xch);
    cudaGetSymbolAddress((void**)&qkv, g_qkv);
    cudaGetSymbolAddress((void**)&headsh, g_headsh);
    cudaGetSymbolAddress((void**)&tmp, g_tmp);
    cudaGetSymbolAddress((void**)&attn_out, g_attnout);
    cudaGetSymbolAddress((void**)&attnouth, g_attnouth);
    cudaGetSymbolAddress((void**)&ffnh, g_ffnh);
    cudaGetSymbolAddress((void**)&wqkvT, g_wqkvT);
    cudaGetSymbolAddress((void**)&projwT, g_projwT);
    cudaGetSymbolAddress((void**)&w1T, g_w1T);
    cudaGetSymbolAddress((void**)&w2T, g_w2T);
    cudaGetSymbolAddress((void**)&idx, g_idx);
    cudaGetSymbolAddress((void**)&nk, g_nkeep);

    static int smem_set = 0;
    if (!smem_set) {
        cudaFuncSetAttribute(attention_tc, cudaFuncAttributeMaxDynamicSharedMemorySize,
                             ATT_SMEM_FLOATS * 4);
        cudaFuncSetAttribute(hgemm, cudaFuncAttributeMaxDynamicSharedMemorySize, HSM_TOTAL);
        smem_set = 1;
    }
    const int att_smem = ATT_SMEM_FLOATS * 4;

    // 1. skipper + gather (fp32 residual + fp16 copy)
    skipper_scan<<<BB, SS>>>(keepm, idx, nk);
    gather_kernel<<<MTOT, 128>>>(x, idx, nk, xc, xch);

    // 2. weight prep (transpose to [N][K], fp16)
    pack_wqkv_t<<<(1536 * 512) / 256, 256>>>(w_qs, w_ks, w_vs, wqkvT);
    transpose_half<<<dim3(DM / 32, DM / 32), dim3(32, 8)>>>(proj_w, projwT, DM, DM);
    transpose_half<<<dim3(DINNER / 32, DM / 32), dim3(32, 8)>>>(ffn_w1, w1T, DM, DINNER);
    transpose_half<<<dim3(DM / 32, DINNER / 32), dim3(32, 8)>>>(ffn_w2, w2T, DINNER, DM);

    // 3. fused QKV projection: [16384,512] @ [512,1536] -> fp32 qkv
    hgemm<<<dim3(1536 / 128, MTOT / 128), 256, HSM_TOTAL>>>(
        xch, wqkvT, qkv, nullptr, MTOT, 1536, DM, nullptr, 0);

    // 4. attention (writes attns fp32 + heads fp16)
    attention_tc<<<dim3(BB * NH, SS / 64), 256, att_smem>>>(qkv, nk, attns, headsh);

    // 5. output projection + LN1
    hgemm<<<dim3(DM / 128, MTOT / 128), 256, HSM_TOTAL>>>(
        headsh, projwT, tmp, nullptr, MTOT, DM, DM, proj_b, 0);
    ln_kernel<<<MTOT, 128>>>(tmp, xc, ln1_g, ln1_b, attn_out, attnouth);

    // 6. FFN
    hgemm<<<dim3(DINNER / 128, MTOT / 128), 256, HSM_TOTAL>>>(
        attnouth, w1T, nullptr, ffnh, MTOT, DINNER, DM, ffn_b1, 1);
    hgemm<<<dim3(DM / 128, MTOT / 128), 256, HSM_TOTAL>>>(
        ffnh, w2T, tmp, nullptr, MTOT, DM, DINNER, ffn_b2, 0);
    ln_kernel<<<MTOT, 128>>>(tmp, attn_out, ln2_g, ln2_b, enc_out, nullptr);
}

// round 8
// speedup vs baseline: 9.7015x; 1.5071x over previous
#include <cuda_runtime.h>
#include <cuda_fp16.h>
#include <math.h>
#include <stdint.h>

// ---------------- problem constants ----------------
#define BB 32
#define SS 512
#define DM 512
#define NH 8
#define DK 64
#define DINNER 2048
#define MTOT (BB * SS)              // 16384 rows
#define ENC_ELEMS (BB * SS * DM)    // 8388608
#define EPSLN 1e-3f

// ---------------- scratch (device globals; no allocation allowed) ----------------
__device__ float  g_xc[MTOT * DM];          // compacted input (fp32 residual)
__device__ __half g_xch[MTOT * DM];         // fp16 copy (GEMM A)
__device__ __half g_qkvh[MTOT * 3 * DM];    // merged q|k|v  [row][1536] fp16
__device__ __half g_headsh[MTOT * DM];      // attn heads (fp16)
__device__ float  g_tmp[MTOT * DM];         // pre-LN gemm out
__device__ float  g_attnout[MTOT * DM];     // LN1 output (fp32 residual)
__device__ __half g_attnouth[MTOT * DM];    // LN1 output (fp16)
__device__ __half g_ffnh[MTOT * DINNER];    // FFN hidden (fp16, relu'd)
__device__ __half g_wqkvT[1536 * DM];       // [n][k] fp16
__device__ __half g_projwT[DM * DM];
__device__ __half g_w1T[DINNER * DM];
__device__ __half g_w2T[DM * DINNER];
__device__ int    g_idx[BB * SS];
__device__ int    g_nkeep[BB];

// ---------------- helpers ----------------
__device__ __forceinline__ void cpa16(uint32_t dst, const void* src) {
    asm volatile("cp.async.cg.shared.global [%0], [%1], 16;" :: "r"(dst), "l"(src));
}
__device__ __forceinline__ void ldm_x4(uint32_t* r, uint32_t addr) {
    asm volatile("ldmatrix.sync.aligned.m8n8.x4.shared.b16 {%0,%1,%2,%3}, [%4];"
                 : "=r"(r[0]), "=r"(r[1]), "=r"(r[2]), "=r"(r[3]) : "r"(addr));
}
__device__ __forceinline__ void ldm_x4_t(uint32_t* r, uint32_t addr) {
    asm volatile("ldmatrix.sync.aligned.m8n8.x4.trans.shared.b16 {%0,%1,%2,%3}, [%4];"
                 : "=r"(r[0]), "=r"(r[1]), "=r"(r[2]), "=r"(r[3]) : "r"(addr));
}
__device__ __forceinline__ void mma_f16(float* d, const uint32_t* a, uint32_t b0, uint32_t b1) {
    asm volatile(
        "mma.sync.aligned.m16n8k16.row.col.f32.f16.f16.f32 "
        "{%0,%1,%2,%3}, {%4,%5,%6,%7}, {%8,%9}, {%0,%1,%2,%3};"
        : "+f"(d[0]), "+f"(d[1]), "+f"(d[2]), "+f"(d[3])
        : "r"(a[0]), "r"(a[1]), "r"(a[2]), "r"(a[3]), "r"(b0), "r"(b1));
}
__device__ __forceinline__ float fast_exp(float x) {
    float t = x * 1.4426950408889634f;
    float z = t + 12582912.0f;
    int   m = __float_as_int(z) - 0x4B400000;
    float f = t - (z - 12582912.0f);
    float p = 1.3333558146e-3f;
    p = fmaf(p, f, 9.6181291076e-3f);
    p = fmaf(p, f, 5.5504108665e-2f);
    p = fmaf(p, f, 2.4022650696e-1f);
    p = fmaf(p, f, 6.9314718056e-1f);
    p = fmaf(p, f, 1.0f);
    return __int_as_float(__float_as_int(p) + (m << 23));
}
__device__ __forceinline__ uint32_t smem_u32(const void* p) {
    uint32_t a;
    asm("{ .reg .u64 t; cvta.to.shared.u64 t, %1; cvt.u32.u64 %0, t; }" : "=r"(a) : "l"(p));
    return a;
}

// ---------------- skipper ----------------
__global__ void skipper_scan(const int* __restrict__ keep, int* __restrict__ idx,
                             int* __restrict__ nkeep) {
    int b = blockIdx.x, t = threadIdx.x;
    __shared__ int sh[SS];
    int v = keep[b * SS + t] > 0;
    sh[t] = v;
    __syncthreads();
    for (int off = 1; off < SS; off <<= 1) {
        int x = (t >= off) ? sh[t - off] : 0;
        __syncthreads();
        sh[t] += x;
        __syncthreads();
    }
    int incl = sh[t];
    if (v) idx[b * SS + incl - 1] = t;
    if (t == SS - 1) nkeep[b] = incl;
}

__global__ void gather_kernel(const float* __restrict__ x, const int* __restrict__ idx,
                              const int* __restrict__ nkeep, float* __restrict__ xc,
                              __half* __restrict__ xch) {
    int bs = blockIdx.x;
    int b = bs >> 9, s = bs & 511;
    int nk = nkeep[b];
    float4 v = make_float4(0.f, 0.f, 0.f, 0.f);
    if (s < nk)
        v = ((const float4*)(x + ((size_t)b * SS + idx[b * SS + s]) * DM))[threadIdx.x];
    ((float4*)(xc + (size_t)bs * DM))[threadIdx.x] = v;
    __half2 h0 = __floats2half2_rn(v.x, v.y);
    __half2 h1 = __floats2half2_rn(v.z, v.w);
    uint2 u;
    u.x = *(uint32_t*)&h0;
    u.y = *(uint32_t*)&h1;
    ((uint2*)(xch + (size_t)bs * DM))[threadIdx.x] = u;
}

// pack per-head weights [H, D, 64] x3 -> transposed [1536][512] fp16
__global__ void pack_wqkv_t(const float* __restrict__ wq, const float* __restrict__ wk,
                            const float* __restrict__ wv, __half* __restrict__ wp) {
    int i = blockIdx.x * 256 + threadIdx.x;  // over 1536*512
    int n = i >> 9;
    int d = i & 511;
    int sel = n >> 9;
    int nn = n & 511;
    int h = nn >> 6, kk = nn & 63;
    const float* w = (sel == 0) ? wq : (sel == 1) ? wk : wv;
    wp[i] = __float2half_rn(w[(h * DM + d) * DK + kk]);
}

// transpose [R][C] fp32 -> [C][R] fp16
__global__ void transpose_half(const float* __restrict__ in, __half* __restrict__ out,
                               int R, int C) {
    __shared__ float t[32][33];
    int c0 = blockIdx.x * 32, r0 = blockIdx.y * 32;
    int x = threadIdx.x, y = threadIdx.y;  // 32 x 8
#pragma unroll
    for (int j = 0; j < 32; j += 8)
        t[y + j][x] = in[(size_t)(r0 + y + j) * C + c0 + x];
    __syncthreads();
#pragma unroll
    for (int j = 0; j < 32; j += 8)
        out[(size_t)(c0 + y + j) * R + r0 + x] = __float2half_rn(t[x][y + j]);
}

// ---------------- fp16 tensor-core GEMM (128x128 tile, BK=64) ----------------
#define HSM_TOTAL 65536

__global__ void __launch_bounds__(256, 2) hgemm(
    const __half* __restrict__ A, const __half* __restrict__ Bt,
    float* __restrict__ Cf, __half* __restrict__ Ch,
    int M, int N, int K, const float* __restrict__ bias, int relu) {
    extern __shared__ __align__(128) char smc[];
    uint32_t sbase = smem_u32(smc);

    int tid = threadIdx.x;
    int wid = tid >> 5, lane = tid & 31;
    int g = lane >> 2, t4 = lane & 3;
    int l15 = lane & 15, l16 = lane >> 4;
    int wm = wid >> 2, wn = wid & 3;
    int rowBase = blockIdx.y * 128;
    int colBase = blockIdx.x * 128;

    float acc[4][4][4];
#pragma unroll
    for (int i = 0; i < 4; i++)
#pragma unroll
        for (int j = 0; j < 4; j++)
#pragma unroll
            for (int c = 0; c < 4; c++) acc[i][j][c] = 0.f;

    const int nc = K / 64;

    auto load_tile = [&](int kt, int buf) {
        int k0 = kt * 64;
#pragma unroll
        for (int j = 0; j < 4; j++) {
            int cid = tid + 256 * j;
            int row = cid >> 3, c = cid & 7;
            uint32_t off = row * 128 + ((c ^ (row & 7)) << 4);
            cpa16(sbase + buf * 16384 + off,
                  A + (size_t)(rowBase + row) * K + k0 + c * 8);
            cpa16(sbase + 32768 + buf * 16384 + off,
                  Bt + (size_t)(colBase + row) * K + k0 + c * 8);
        }
        asm volatile("cp.async.commit_group;");
    };

    load_tile(0, 0);
    if (nc > 1) load_tile(1, 1);

    for (int kt = 0; kt < nc; kt++) {
        int buf = kt & 1;
        if (kt + 2 < nc) {
            asm volatile("cp.async.wait_group 1;");
        } else {
            asm volatile("cp.async.wait_group 0;");
        }
        __syncthreads();

        uint32_t aBase = sbase + buf * 16384;
        uint32_t bBase = sbase + 32768 + buf * 16384;
#pragma unroll
        for (int ks = 0; ks < 4; ks++) {
            int ch = 2 * ks + l16;
            uint32_t a[4][4];
#pragma unroll
            for (int mt = 0; mt < 4; mt++) {
                int row = wm * 64 + mt * 16 + l15;
                ldm_x4(a[mt], aBase + row * 128 + ((ch ^ (row & 7)) << 4));
            }
            uint32_t bq[2][4];
#pragma unroll
            for (int bt = 0; bt < 2; bt++) {
                int row = wn * 32 + bt * 16 + l15;
                ldm_x4(bq[bt], bBase + row * 128 + ((ch ^ (row & 7)) << 4));
            }
#pragma unroll
            for (int mt = 0; mt < 4; mt++)
#pragma unroll
                for (int nt = 0; nt < 4; nt++)
                    mma_f16(acc[mt][nt], a[mt], bq[nt >> 1][nt & 1], bq[nt >> 1][2 + (nt & 1)]);
        }
        __syncthreads();

        if (kt + 2 < nc) load_tile(kt + 2, buf);
    }

#pragma unroll
    for (int mt = 0; mt < 4; mt++) {
        int r0 = rowBase + wm * 64 + mt * 16 + g;
#pragma unroll
        for (int nt = 0; nt < 4; nt++) {
            int c = colBase + wn * 32 + nt * 8 + 2 * t4;
            float b0 = bias ? __ldg(bias + c) : 0.f;
            float b1 = bias ? __ldg(bias + c + 1) : 0.f;
            float v0 = acc[mt][nt][0] + b0, v1 = acc[mt][nt][1] + b1;
            float v2 = acc[mt][nt][2] + b0, v3 = acc[mt][nt][3] + b1;
            if (relu) {
                v0 = fmaxf(v0, 0.f); v1 = fmaxf(v1, 0.f);
                v2 = fmaxf(v2, 0.f); v3 = fmaxf(v3, 0.f);
            }
            if (Cf) {
                *(float2*)(Cf + (size_t)r0 * N + c) = make_float2(v0, v1);
                *(float2*)(Cf + (size_t)(r0 + 8) * N + c) = make_float2(v2, v3);
            }
            if (Ch) {
                *(__half2*)(Ch + (size_t)r0 * N + c) = __floats2half2_rn(v0, v1);
                *(__half2*)(Ch + (size_t)(r0 + 8) * N + c) = __floats2half2_rn(v2, v3);
            }
        }
    }
}

// ---------------- fp16 tensor-core attention ----------------
// block = (b,h) x 64-row s-tile, 256 threads / 8 warps, 2 CTA/SM.
// smem (halves strides): Q[64][72], KV[128][72], Es[64][520] fp16, ssum[64] fp32
#define SQ_OFF 0
#define SKV_OFF 9216
#define SE_OFF 27648
#define SSUM_OFF 94208
#define ATT_SMEM 94464

__global__ void __launch_bounds__(256, 2) attention_h(
    const __half* __restrict__ qkv, const int* __restrict__ nkeep,
    float* __restrict__ attns, __half* __restrict__ heads) {
    extern __shared__ __align__(128) char smc[];
    uint32_t sbase = smem_u32(smc);
    uint32_t sQ = sbase + SQ_OFF;
    uint32_t sKV = sbase + SKV_OFF;
    uint32_t sE = sbase + SE_OFF;
    float* ssum = (float*)(smc + SSUM_OFF);
    __half* EsH = (__half*)(smc + SE_OFF);

    int bh = blockIdx.x;
    int b = bh >> 3, h = bh & 7;
    int s0 = blockIdx.y * 64;
    int tid = threadIdx.x;
    int wid = tid >> 5, lane = tid & 31;
    int g = lane >> 2, t4 = lane & 3;
    int l15 = lane & 15, l16 = lane >> 4;
    int nk = nkeep[b];
    const float sc = 0.04419417382415922f;  // 1/sqrt(512)
    const int QS = 3 * DM;                  // 1536 halves per row

    if (tid < 64) ssum[tid] = 0.f;

    // async-load Q tile (64 rows x 64 halves)
#pragma unroll
    for (int j = 0; j < 2; j++) {
        int cid = tid + 256 * j;
        int row = cid >> 3, c = cid & 7;
        cpa16(sQ + row * 144 + c * 16,
              qkv + ((size_t)(b * SS + s0 + row)) * QS + h * 64 + c * 8);
    }
    // async-load K chunk 0 (128 rows x 64 halves)
#pragma unroll
    for (int j = 0; j < 4; j++) {
        int cid = tid + 256 * j;
        int row = cid >> 3, c = cid & 7;
        cpa16(sKV + row * 144 + c * 16,
              qkv + ((size_t)(b * SS + row)) * QS + 512 + h * 64 + c * 8);
    }
    asm volatile("cp.async.commit_group;");
    asm volatile("cp.async.wait_group 0;");
    __syncthreads();

    // ---- Phase A: exp(QK^T * sc) -> Es fp16, partial row sums in regs ----
    int wmA = wid >> 2, wnA = wid & 3;  // 2 x 4; warp tile m32 x n32
    float psum[4] = {0.f, 0.f, 0.f, 0.f};

    for (int t0 = 0; t0 < SS; t0 += 128) {
        float acc[2][4][4];
#pragma unroll
        for (int i = 0; i < 2; i++)
#pragma unroll
            for (int j = 0; j < 4; j++)
#pragma unroll
                for (int c = 0; c < 4; c++) acc[i][j][c] = 0.f;

#pragma unroll
        for (int ks = 0; ks < 4; ks++) {
            uint32_t a[2][4];
#pragma unroll
            for (int mt = 0; mt < 2; mt++) {
                int row = wmA * 32 + mt * 16 + l15;
                ldm_x4(a[mt], sQ + row * 144 + ks * 32 + l16 * 16);
            }
            uint32_t bq[2][4];
#pragma unroll
            for (int bt = 0; bt < 2; bt++) {
                int row = wnA * 32 + bt * 16 + l15;
                ldm_x4(bq[bt], sKV + row * 144 + ks * 32 + l16 * 16);
            }
#pragma unroll
            for (int mt = 0; mt < 2; mt++)
#pragma unroll
                for (int nt = 0; nt < 4; nt++)
                    mma_f16(acc[mt][nt], a[mt], bq[nt >> 1][nt & 1], bq[nt >> 1][2 + (nt & 1)]);
        }
        __syncthreads();  // done reading K chunk

        // prefetch next K chunk
        if (t0 + 128 < SS) {
#pragma unroll
            for (int j = 0; j < 4; j++) {
                int cid = tid + 256 * j;
                int row = cid >> 3, c = cid & 7;
                cpa16(sKV + row * 144 + c * 16,
                      qkv + ((size_t)(b * SS + t0 + 128 + row)) * QS + 512 + h * 64 + c * 8);
            }
            asm volatile("cp.async.commit_group;");
        }

        // exp + mask + store fp16 + accumulate partial row sums
#pragma unroll
        for (int mt = 0; mt < 2; mt++) {
            int r0 = wmA * 32 + mt * 16 + g;
#pragma unroll
            for (int nt = 0; nt < 4; nt++) {
                int col = t0 + wnA * 32 + nt * 8 + 2 * t4;
                float e0 = (col     < nk) ? fast_exp(acc[mt][nt][0] * sc) : 0.f;
                float e1 = (col + 1 < nk) ? fast_exp(acc[mt][nt][1] * sc) : 0.f;
                float e2 = (col     < nk) ? fast_exp(acc[mt][nt][2] * sc) : 0.f;
                float e3 = (col + 1 < nk) ? fast_exp(acc[mt][nt][3] * sc) : 0.f;
                *(__half2*)(EsH + r0 * 520 + col) = __floats2half2_rn(e0, e1);
                *(__half2*)(EsH + (r0 + 8) * 520 + col) = __floats2half2_rn(e2, e3);
                psum[mt * 2 + 0] += e0 + e1;
                psum[mt * 2 + 1] += e2 + e3;
            }
        }

        if (t0 + 128 < SS) {
            asm volatile("cp.async.wait_group 0;");
            __syncthreads();
        }
    }

    // merge partial sums
#pragma unroll
    for (int mt = 0; mt < 2; mt++) {
        atomicAdd(&ssum[wmA * 32 + mt * 16 + g], psum[mt * 2 + 0]);
        atomicAdd(&ssum[wmA * 32 + mt * 16 + g + 8], psum[mt * 2 + 1]);
    }
    __syncthreads();
    if (tid < 64) ssum[tid] = 1.f / ssum[tid];
    __syncthreads();

    // prefetch V chunk 0 while writing attns
#pragma unroll
    for (int j = 0; j < 4; j++) {
        int cid = tid + 256 * j;
        int row = cid >> 3, c = cid & 7;
        cpa16(sKV + row * 144 + c * 16,
              qkv + ((size_t)(b * SS + row)) * QS + 1024 + h * 64 + c * 8);
    }
    asm volatile("cp.async.commit_group;");

    // write normalized P (fp32) to attns
    {
        float* dst = attns + (((size_t)(h * BB + b)) * SS + s0) * SS;
        for (int i = tid; i < 8192; i += 256) {
            int row = i >> 7, c4 = (i & 127) * 4;
            uint2 u = *(uint2*)(EsH + row * 520 + c4);
            float2 f0 = __half22float2(*(__half2*)&u.x);
            float2 f1 = __half22float2(*(__half2*)&u.y);
            float riv = ssum[row];
            *(float4*)(dst + (size_t)row * SS + c4) =
                make_float4(f0.x * riv, f0.y * riv, f1.x * riv, f1.y * riv);
        }
    }
    asm volatile("cp.async.wait_group 0;");
    __syncthreads();

    // ---- Phase B: O = (Es @ V) * rinv ----
    int wmB = wid >> 1, wnB = wid & 1;  // 4 x 2; warp tile m16 x n32
    float oacc[4][4];
#pragma unroll
    for (int j = 0; j < 4; j++)
#pragma unroll
        for (int c = 0; c < 4; c++) oacc[j][c] = 0.f;

    for (int t0 = 0; t0 < SS; t0 += 128) {
#pragma unroll
        for (int k16 = 0; k16 < 8; k16++) {
            uint32_t a[4];
            {
                int row = wmB * 16 + l15;
                ldm_x4(a, sE + row * 1040 + (t0 + k16 * 16) * 2 + l16 * 16);
            }
            uint32_t bt[2][4];
#pragma unroll
            for (int pair = 0; pair < 2; pair++) {
                int kr = k16 * 16 + l15;
                int nv = wnB * 32 + pair * 16 + l16 * 8;
                ldm_x4_t(bt[pair], sKV + kr * 144 + nv * 2);
            }
            // trans-ldmatrix register order: {b0(n-low), b1(n-low), b0(n-high), b1(n-high)}
#pragma unroll
            for (int nt = 0; nt < 4; nt++)
                mma_f16(oacc[nt], a, bt[nt >> 1][(nt & 1) * 2], bt[nt >> 1][(nt & 1) * 2 + 1]);
        }
        __syncthreads();
        if (t0 + 128 < SS) {
#pragma unroll
            for (int j = 0; j < 4; j++) {
                int cid = tid + 256 * j;
                int row = cid >> 3, c = cid & 7;
                cpa16(sKV + row * 144 + c * 16,
                      qkv + ((size_t)(b * SS + t0 + 128 + row)) * QS + 1024 + h * 64 + c * 8);
            }
            asm volatile("cp.async.commit_group;");
            asm volatile("cp.async.wait_group 0;");
            __syncthreads();
        }
    }

    // write O (fp16 heads)
    {
        int r0 = wmB * 16 + g;
        float ri0 = ssum[r0], ri1 = ssum[r0 + 8];
        size_t base0 = ((size_t)(b * SS + s0 + r0)) * DM + h * 64;
        size_t base1 = ((size_t)(b * SS + s0 + r0 + 8)) * DM + h * 64;
#pragma unroll
        for (int nt = 0; nt < 4; nt++) {
            int c = wnB * 32 + nt * 8 + 2 * t4;
            *(__half2*)(heads + base0 + c) =
                __floats2half2_rn(oacc[nt][0] * ri0, oacc[nt][1] * ri0);
            *(__half2*)(heads + base1 + c) =
                __floats2half2_rn(oacc[nt][2] * ri1, oacc[nt][3] * ri1);
        }
    }
}

// ---------------- layernorm with residual; optional fp16 side copy ----------------
__global__ void ln_kernel(const float* __restrict__ y, const float* __restrict__ resid,
                          const float* __restrict__ g, const float* __restrict__ be,
                          float* __restrict__ out, __half* __restrict__ out_h) {
    int row = blockIdx.x;
    int tid = threadIdx.x;  // 128
    float4 a = ((const float4*)(y + (size_t)row * DM))[tid];
    float4 b = ((const float4*)(resid + (size_t)row * DM))[tid];
    float v0 = a.x + b.x, v1 = a.y + b.y, v2 = a.z + b.z, v3 = a.w + b.w;
    float s = v0 + v1 + v2 + v3;
    float ss = v0 * v0 + v1 * v1 + v2 * v2 + v3 * v3;
    for (int o = 16; o; o >>= 1) {
        s += __shfl_xor_sync(~0u, s, o);
        ss += __shfl_xor_sync(~0u, ss, o);
    }
    __shared__ float shs[4], shss[4];
    int w = tid >> 5, l = tid & 31;
    if (l == 0) { shs[w] = s; shss[w] = ss; }
    __syncthreads();
    s = shs[0] + shs[1] + shs[2] + shs[3];
    ss = shss[0] + shss[1] + shss[2] + shss[3];
    float mu = s * (1.f / 512.f);
    float var = fmaxf((ss - 512.f * mu * mu) * (1.f / 511.f), 0.f);
    float inv = 1.f / (sqrtf(var) + EPSLN);
    float4 gg = ((const float4*)g)[tid];
    float4 bb = ((const float4*)be)[tid];
    float4 o;
    o.x = (v0 - mu) * inv * gg.x + bb.x;
    o.y = (v1 - mu) * inv * gg.y + bb.y;
    o.z = (v2 - mu) * inv * gg.z + bb.z;
    o.w = (v3 - mu) * inv * gg.w + bb.w;
    ((float4*)(out + (size_t)row * DM))[tid] = o;
    if (out_h) {
        __half2 h0 = __floats2half2_rn(o.x, o.y);
        __half2 h1 = __floats2half2_rn(o.z, o.w);
        uint2 u;
        u.x = *(uint32_t*)&h0;
        u.y = *(uint32_t*)&h1;
        ((uint2*)(out_h + (size_t)row * DM))[tid] = u;
    }
}

// ---------------- launch ----------------
extern "C" void kernel_launch(void* const* d_in, const int* in_sizes, int n_in,
                              void* d_out, int out_size) {
    const float* x      = (const float*)d_in[0];
    const float* w_qs   = (const float*)d_in[1];
    const float* w_ks   = (const float*)d_in[2];
    const float* w_vs   = (const float*)d_in[3];
    const float* proj_w = (const float*)d_in[4];
    const float* proj_b = (const float*)d_in[5];
    const float* ln1_g  = (const float*)d_in[6];
    const float* ln1_b  = (const float*)d_in[7];
    const float* ffn_w1 = (const float*)d_in[8];
    const float* ffn_b1 = (const float*)d_in[9];
    const float* ffn_w2 = (const float*)d_in[10];
    const float* ffn_b2 = (const float*)d_in[11];
    const float* ln2_g  = (const float*)d_in[12];
    const float* ln2_b  = (const float*)d_in[13];
    const int*   keepm  = (const int*)d_in[14];

    float* out = (float*)d_out;
    float* enc_out = out;
    float* attns   = out + ENC_ELEMS;

    float *xc, *tmp, *attn_out;
    __half *xch, *qkvh, *headsh, *attnouth, *ffnh, *wqkvT, *projwT, *w1T, *w2T;
    int *idx, *nk;
    cudaGetSymbolAddress((void**)&xc, g_xc);
    cudaGetSymbolAddress((void**)&xch, g_xch);
    cudaGetSymbolAddress((void**)&qkvh, g_qkvh);
    cudaGetSymbolAddress((void**)&headsh, g_headsh);
    cudaGetSymbolAddress((void**)&tmp, g_tmp);
    cudaGetSymbolAddress((void**)&attn_out, g_attnout);
    cudaGetSymbolAddress((void**)&attnouth, g_attnouth);
    cudaGetSymbolAddress((void**)&ffnh, g_ffnh);
    cudaGetSymbolAddress((void**)&wqkvT, g_wqkvT);
    cudaGetSymbolAddress((void**)&projwT, g_projwT);
    cudaGetSymbolAddress((void**)&w1T, g_w1T);
    cudaGetSymbolAddress((void**)&w2T, g_w2T);
    cudaGetSymbolAddress((void**)&idx, g_idx);
    cudaGetSymbolAddress((void**)&nk, g_nkeep);

    static int smem_set = 0;
    if (!smem_set) {
        cudaFuncSetAttribute(attention_h, cudaFuncAttributeMaxDynamicSharedMemorySize, ATT_SMEM);
        cudaFuncSetAttribute(hgemm, cudaFuncAttributeMaxDynamicSharedMemorySize, HSM_TOTAL);
        smem_set = 1;
    }

    // 1. skipper + gather
    skipper_scan<<<BB, SS>>>(keepm, idx, nk);
    gather_kernel<<<MTOT, 128>>>(x, idx, nk, xc, xch);

    // 2. weight prep
    pack_wqkv_t<<<(1536 * 512) / 256, 256>>>(w_qs, w_ks, w_vs, wqkvT);
    transpose_half<<<dim3(DM / 32, DM / 32), dim3(32, 8)>>>(proj_w, projwT, DM, DM);
    transpose_half<<<dim3(DINNER / 32, DM / 32), dim3(32, 8)>>>(ffn_w1, w1T, DM, DINNER);
    transpose_half<<<dim3(DM / 32, DINNER / 32), dim3(32, 8)>>>(ffn_w2, w2T, DINNER, DM);

    // 3. fused QKV projection -> fp16 qkv
    hgemm<<<dim3(1536 / 128, MTOT / 128), 256, HSM_TOTAL>>>(
        xch, wqkvT, nullptr, qkvh, MTOT, 1536, DM, nullptr, 0);

    // 4. fp16 attention (writes attns fp32 + heads fp16)
    attention_h<<<dim3(BB * NH, SS / 64), 256, ATT_SMEM>>>(qkvh, nk, attns, headsh);

    // 5. output projection + LN1
    hgemm<<<dim3(DM / 128, MTOT / 128), 256, HSM_TOTAL>>>(
        headsh, projwT, tmp, nullptr, MTOT, DM, DM, proj_b, 0);
    ln_kernel<<<MTOT, 128>>>(tmp, xc, ln1_g, ln1_b, attn_out, attnouth);

    // 6. FFN
    hgemm<<<dim3(DINNER / 128, MTOT / 128), 256, HSM_TOTAL>>>(
        attnouth, w1T, nullptr, ffnh, MTOT, DINNER, DM, ffn_b1, 1);
    hgemm<<<dim3(DM / 128, MTOT / 128), 256, HSM_TOTAL>>>(
        ffnh, w2T, tmp, nullptr, MTOT, DM, DINNER, ffn_b2, 0);
    ln_kernel<<<MTOT, 128>>>(tmp, attn_out, ln2_g, ln2_b, enc_out, nullptr);
}

// round 9
// speedup vs baseline: 10.0076x; 1.0316x over previous
#include <cuda_runtime.h>
#include <cuda_fp16.h>
#include <math.h>
#include <stdint.h>

// ---------------- problem constants ----------------
#define BB 32
#define SS 512
#define DM 512
#define NH 8
#define DK 64
#define DINNER 2048
#define MTOT (BB * SS)              // 16384 rows
#define ENC_ELEMS (BB * SS * DM)    // 8388608
#define EPSLN 1e-3f

// ---------------- scratch (device globals; no allocation allowed) ----------------
__device__ __half g_xch[MTOT * DM];         // compacted input fp16 (GEMM A + LN1 residual)
__device__ __half g_qkvh[MTOT * 3 * DM];    // merged q|k|v  [row][1536] fp16
__device__ __half g_headsh[MTOT * DM];      // attn heads (fp16)
__device__ __half g_tmph[MTOT * DM];        // pre-LN gemm out (fp16, reused)
__device__ __half g_attnouth[MTOT * DM];    // LN1 output (fp16)
__device__ __half g_ffnh[MTOT * DINNER];    // FFN hidden (fp16, relu'd)
__device__ __half g_wqkvT[1536 * DM];       // [n][k] fp16
__device__ __half g_projwT[DM * DM];
__device__ __half g_w1T[DINNER * DM];
__device__ __half g_w2T[DM * DINNER];
__device__ int    g_idx[BB * SS];
__device__ int    g_nkeep[BB];

// ---------------- helpers ----------------
__device__ __forceinline__ void cpa16(uint32_t dst, const void* src) {
    asm volatile("cp.async.cg.shared.global [%0], [%1], 16;" :: "r"(dst), "l"(src));
}
__device__ __forceinline__ void ldm_x4(uint32_t* r, uint32_t addr) {
    asm volatile("ldmatrix.sync.aligned.m8n8.x4.shared.b16 {%0,%1,%2,%3}, [%4];"
                 : "=r"(r[0]), "=r"(r[1]), "=r"(r[2]), "=r"(r[3]) : "r"(addr));
}
__device__ __forceinline__ void ldm_x4_t(uint32_t* r, uint32_t addr) {
    asm volatile("ldmatrix.sync.aligned.m8n8.x4.trans.shared.b16 {%0,%1,%2,%3}, [%4];"
                 : "=r"(r[0]), "=r"(r[1]), "=r"(r[2]), "=r"(r[3]) : "r"(addr));
}
__device__ __forceinline__ void mma_f16(float* d, const uint32_t* a, uint32_t b0, uint32_t b1) {
    asm volatile(
        "mma.sync.aligned.m16n8k16.row.col.f32.f16.f16.f32 "
        "{%0,%1,%2,%3}, {%4,%5,%6,%7}, {%8,%9}, {%0,%1,%2,%3};"
        : "+f"(d[0]), "+f"(d[1]), "+f"(d[2]), "+f"(d[3])
        : "r"(a[0]), "r"(a[1]), "r"(a[2]), "r"(a[3]), "r"(b0), "r"(b1));
}
__device__ __forceinline__ float fast_exp(float x) {
    float t = x * 1.4426950408889634f;
    float z = t + 12582912.0f;
    int   m = __float_as_int(z) - 0x4B400000;
    float f = t - (z - 12582912.0f);
    float p = 1.3333558146e-3f;
    p = fmaf(p, f, 9.6181291076e-3f);
    p = fmaf(p, f, 5.5504108665e-2f);
    p = fmaf(p, f, 2.4022650696e-1f);
    p = fmaf(p, f, 6.9314718056e-1f);
    p = fmaf(p, f, 1.0f);
    return __int_as_float(__float_as_int(p) + (m << 23));
}
__device__ __forceinline__ uint32_t smem_u32(const void* p) {
    uint32_t a;
    asm("{ .reg .u64 t; cvta.to.shared.u64 t, %1; cvt.u32.u64 %0, t; }" : "=r"(a) : "l"(p));
    return a;
}
__device__ __forceinline__ void stcs4(float* p, float4 v) {
    asm volatile("st.global.cs.v4.f32 [%0], {%1,%2,%3,%4};"
                 :: "l"(p), "f"(v.x), "f"(v.y), "f"(v.z), "f"(v.w) : "memory");
}

// ---------------- weight prep: 3 transposes fused (one launch) ----------------
__global__ void prep_weights(const float* __restrict__ proj_w, const float* __restrict__ w1,
                             const float* __restrict__ w2, __half* __restrict__ projwT,
                             __half* __restrict__ w1T, __half* __restrict__ w2T) {
    __shared__ float t[32][33];
    int z = blockIdx.z;
    const float* in;
    __half* out;
    int R, C;
    if (z == 0)      { in = proj_w; out = projwT; R = DM;     C = DM; }
    else if (z == 1) { in = w1;     out = w1T;    R = DM;     C = DINNER; }
    else             { in = w2;     out = w2T;    R = DINNER; C = DM; }
    int c0 = blockIdx.x * 32, r0 = blockIdx.y * 32;
    if (c0 >= C || r0 >= R) return;
    int x = threadIdx.x, y = threadIdx.y;  // 32 x 8
#pragma unroll
    for (int j = 0; j < 32; j += 8)
        t[y + j][x] = in[(size_t)(r0 + y + j) * C + c0 + x];
    __syncthreads();
#pragma unroll
    for (int j = 0; j < 32; j += 8)
        out[(size_t)(c0 + y + j) * R + r0 + x] = __float2half_rn(t[x][y + j]);
}

// pack per-head weights [H, D, 64] x3 -> transposed [1536][512] fp16
__global__ void pack_wqkv_t(const float* __restrict__ wq, const float* __restrict__ wk,
                            const float* __restrict__ wv, __half* __restrict__ wp) {
    int i = blockIdx.x * 256 + threadIdx.x;  // over 1536*512
    int n = i >> 9;
    int d = i & 511;
    int sel = n >> 9;
    int nn = n & 511;
    int h = nn >> 6, kk = nn & 63;
    const float* w = (sel == 0) ? wq : (sel == 1) ? wk : wv;
    wp[i] = __float2half_rn(w[(h * DM + d) * DK + kk]);
}

// ---------------- skipper ----------------
__global__ void skipper_scan(const int* __restrict__ keep, int* __restrict__ idx,
                             int* __restrict__ nkeep) {
    int b = blockIdx.x, t = threadIdx.x;
    __shared__ int sh[SS];
    int v = keep[b * SS + t] > 0;
    sh[t] = v;
    __syncthreads();
    for (int off = 1; off < SS; off <<= 1) {
        int x = (t >= off) ? sh[t - off] : 0;
        __syncthreads();
        sh[t] += x;
        __syncthreads();
    }
    int incl = sh[t];
    if (v) idx[b * SS + incl - 1] = t;
    if (t == SS - 1) nkeep[b] = incl;
}

__global__ void gather_kernel(const float* __restrict__ x, const int* __restrict__ idx,
                              const int* __restrict__ nkeep, __half* __restrict__ xch) {
    int bs = blockIdx.x;
    int b = bs >> 9, s = bs & 511;
    int nk = nkeep[b];
    float4 v = make_float4(0.f, 0.f, 0.f, 0.f);
    if (s < nk)
        v = ((const float4*)(x + ((size_t)b * SS + idx[b * SS + s]) * DM))[threadIdx.x];
    __half2 h0 = __floats2half2_rn(v.x, v.y);
    __half2 h1 = __floats2half2_rn(v.z, v.w);
    uint2 u;
    u.x = *(uint32_t*)&h0;
    u.y = *(uint32_t*)&h1;
    ((uint2*)(xch + (size_t)bs * DM))[threadIdx.x] = u;
}

// ---------------- fp16 tensor-core GEMM (128x128 tile, BK=64) ----------------
#define HSM_TOTAL 65536

__global__ void __launch_bounds__(256, 2) hgemm(
    const __half* __restrict__ A, const __half* __restrict__ Bt,
    float* __restrict__ Cf, __half* __restrict__ Ch,
    int M, int N, int K, const float* __restrict__ bias, int relu) {
    extern __shared__ __align__(128) char smc[];
    uint32_t sbase = smem_u32(smc);

    int tid = threadIdx.x;
    int wid = tid >> 5, lane = tid & 31;
    int g = lane >> 2, t4 = lane & 3;
    int l15 = lane & 15, l16 = lane >> 4;
    int wm = wid >> 2, wn = wid & 3;
    int rowBase = blockIdx.y * 128;
    int colBase = blockIdx.x * 128;

    float acc[4][4][4];
#pragma unroll
    for (int i = 0; i < 4; i++)
#pragma unroll
        for (int j = 0; j < 4; j++)
#pragma unroll
            for (int c = 0; c < 4; c++) acc[i][j][c] = 0.f;

    const int nc = K / 64;

    auto load_tile = [&](int kt, int buf) {
        int k0 = kt * 64;
#pragma unroll
        for (int j = 0; j < 4; j++) {
            int cid = tid + 256 * j;
            int row = cid >> 3, c = cid & 7;
            uint32_t off = row * 128 + ((c ^ (row & 7)) << 4);
            cpa16(sbase + buf * 16384 + off,
                  A + (size_t)(rowBase + row) * K + k0 + c * 8);
            cpa16(sbase + 32768 + buf * 16384 + off,
                  Bt + (size_t)(colBase + row) * K + k0 + c * 8);
        }
        asm volatile("cp.async.commit_group;");
    };

    load_tile(0, 0);
    if (nc > 1) load_tile(1, 1);

    for (int kt = 0; kt < nc; kt++) {
        int buf = kt & 1;
        if (kt + 2 < nc) {
            asm volatile("cp.async.wait_group 1;");
        } else {
            asm volatile("cp.async.wait_group 0;");
        }
        __syncthreads();

        uint32_t aBase = sbase + buf * 16384;
        uint32_t bBase = sbase + 32768 + buf * 16384;
#pragma unroll
        for (int ks = 0; ks < 4; ks++) {
            int ch = 2 * ks + l16;
            uint32_t a[4][4];
#pragma unroll
            for (int mt = 0; mt < 4; mt++) {
                int row = wm * 64 + mt * 16 + l15;
                ldm_x4(a[mt], aBase + row * 128 + ((ch ^ (row & 7)) << 4));
            }
            uint32_t bq[2][4];
#pragma unroll
            for (int bt = 0; bt < 2; bt++) {
                int row = wn * 32 + bt * 16 + l15;
                ldm_x4(bq[bt], bBase + row * 128 + ((ch ^ (row & 7)) << 4));
            }
#pragma unroll
            for (int mt = 0; mt < 4; mt++)
#pragma unroll
                for (int nt = 0; nt < 4; nt++)
                    mma_f16(acc[mt][nt], a[mt], bq[nt >> 1][nt & 1], bq[nt >> 1][2 + (nt & 1)]);
        }
        __syncthreads();

        if (kt + 2 < nc) load_tile(kt + 2, buf);
    }

#pragma unroll
    for (int mt = 0; mt < 4; mt++) {
        int r0 = rowBase + wm * 64 + mt * 16 + g;
#pragma unroll
        for (int nt = 0; nt < 4; nt++) {
            int c = colBase + wn * 32 + nt * 8 + 2 * t4;
            float b0 = bias ? __ldg(bias + c) : 0.f;
            float b1 = bias ? __ldg(bias + c + 1) : 0.f;
            float v0 = acc[mt][nt][0] + b0, v1 = acc[mt][nt][1] + b1;
            float v2 = acc[mt][nt][2] + b0, v3 = acc[mt][nt][3] + b1;
            if (relu) {
                v0 = fmaxf(v0, 0.f); v1 = fmaxf(v1, 0.f);
                v2 = fmaxf(v2, 0.f); v3 = fmaxf(v3, 0.f);
            }
            if (Cf) {
                *(float2*)(Cf + (size_t)r0 * N + c) = make_float2(v0, v1);
                *(float2*)(Cf + (size_t)(r0 + 8) * N + c) = make_float2(v2, v3);
            }
            if (Ch) {
                *(__half2*)(Ch + (size_t)r0 * N + c) = __floats2half2_rn(v0, v1);
                *(__half2*)(Ch + (size_t)(r0 + 8) * N + c) = __floats2half2_rn(v2, v3);
            }
        }
    }
}

// ---------------- fp16 tensor-core attention ----------------
// block = (b,h) x 64-row s-tile, 256 threads / 8 warps, 2 CTA/SM.
// smem (halves strides): Q[64][72], KV[128][72], Es[64][520] fp16, ssum[64] fp32
#define SQ_OFF 0
#define SKV_OFF 9216
#define SE_OFF 27648
#define SSUM_OFF 94208
#define ATT_SMEM 94464

__global__ void __launch_bounds__(256, 2) attention_h(
    const __half* __restrict__ qkv, const int* __restrict__ nkeep,
    float* __restrict__ attns, __half* __restrict__ heads) {
    extern __shared__ __align__(128) char smc[];
    uint32_t sbase = smem_u32(smc);
    uint32_t sQ = sbase + SQ_OFF;
    uint32_t sKV = sbase + SKV_OFF;
    uint32_t sE = sbase + SE_OFF;
    float* ssum = (float*)(smc + SSUM_OFF);
    __half* EsH = (__half*)(smc + SE_OFF);

    int bh = blockIdx.x;
    int b = bh >> 3, h = bh & 7;
    int s0 = blockIdx.y * 64;
    int tid = threadIdx.x;
    int wid = tid >> 5, lane = tid & 31;
    int g = lane >> 2, t4 = lane & 3;
    int l15 = lane & 15, l16 = lane >> 4;
    int nk = nkeep[b];
    const float sc = 0.04419417382415922f;  // 1/sqrt(512)
    const int QS = 3 * DM;                  // 1536 halves per row

    if (tid < 64) ssum[tid] = 0.f;

    // async-load Q tile (64 rows x 64 halves)
#pragma unroll
    for (int j = 0; j < 2; j++) {
        int cid = tid + 256 * j;
        int row = cid >> 3, c = cid & 7;
        cpa16(sQ + row * 144 + c * 16,
              qkv + ((size_t)(b * SS + s0 + row)) * QS + h * 64 + c * 8);
    }
    // async-load K chunk 0 (128 rows x 64 halves)
#pragma unroll
    for (int j = 0; j < 4; j++) {
        int cid = tid + 256 * j;
        int row = cid >> 3, c = cid & 7;
        cpa16(sKV + row * 144 + c * 16,
              qkv + ((size_t)(b * SS + row)) * QS + 512 + h * 64 + c * 8);
    }
    asm volatile("cp.async.commit_group;");
    asm volatile("cp.async.wait_group 0;");
    __syncthreads();

    // ---- Phase A: exp(QK^T * sc) -> Es fp16, partial row sums in regs ----
    int wmA = wid >> 2, wnA = wid & 3;  // 2 x 4; warp tile m32 x n32
    float psum[4] = {0.f, 0.f, 0.f, 0.f};

    for (int t0 = 0; t0 < SS; t0 += 128) {
        float acc[2][4][4];
#pragma unroll
        for (int i = 0; i < 2; i++)
#pragma unroll
            for (int j = 0; j < 4; j++)
#pragma unroll
                for (int c = 0; c < 4; c++) acc[i][j][c] = 0.f;

#pragma unroll
        for (int ks = 0; ks < 4; ks++) {
            uint32_t a[2][4];
#pragma unroll
            for (int mt = 0; mt < 2; mt++) {
                int row = wmA * 32 + mt * 16 + l15;
                ldm_x4(a[mt], sQ + row * 144 + ks * 32 + l16 * 16);
            }
            uint32_t bq[2][4];
#pragma unroll
            for (int bt = 0; bt < 2; bt++) {
                int row = wnA * 32 + bt * 16 + l15;
                ldm_x4(bq[bt], sKV + row * 144 + ks * 32 + l16 * 16);
            }
#pragma unroll
            for (int mt = 0; mt < 2; mt++)
#pragma unroll
                for (int nt = 0; nt < 4; nt++)
                    mma_f16(acc[mt][nt], a[mt], bq[nt >> 1][nt & 1], bq[nt >> 1][2 + (nt & 1)]);
        }
        __syncthreads();  // done reading K chunk

        // prefetch next K chunk
        if (t0 + 128 < SS) {
#pragma unroll
            for (int j = 0; j < 4; j++) {
                int cid = tid + 256 * j;
                int row = cid >> 3, c = cid & 7;
                cpa16(sKV + row * 144 + c * 16,
                      qkv + ((size_t)(b * SS + t0 + 128 + row)) * QS + 512 + h * 64 + c * 8);
            }
            asm volatile("cp.async.commit_group;");
        }

        // exp + mask + store fp16 + accumulate partial row sums
#pragma unroll
        for (int mt = 0; mt < 2; mt++) {
            int r0 = wmA * 32 + mt * 16 + g;
#pragma unroll
            for (int nt = 0; nt < 4; nt++) {
                int col = t0 + wnA * 32 + nt * 8 + 2 * t4;
                float e0 = (col     < nk) ? fast_exp(acc[mt][nt][0] * sc) : 0.f;
                float e1 = (col + 1 < nk) ? fast_exp(acc[mt][nt][1] * sc) : 0.f;
                float e2 = (col     < nk) ? fast_exp(acc[mt][nt][2] * sc) : 0.f;
                float e3 = (col + 1 < nk) ? fast_exp(acc[mt][nt][3] * sc) : 0.f;
                *(__half2*)(EsH + r0 * 520 + col) = __floats2half2_rn(e0, e1);
                *(__half2*)(EsH + (r0 + 8) * 520 + col) = __floats2half2_rn(e2, e3);
                psum[mt * 2 + 0] += e0 + e1;
                psum[mt * 2 + 1] += e2 + e3;
            }
        }

        if (t0 + 128 < SS) {
            asm volatile("cp.async.wait_group 0;");
            __syncthreads();
        }
    }

    // merge partial sums
#pragma unroll
    for (int mt = 0; mt < 2; mt++) {
        atomicAdd(&ssum[wmA * 32 + mt * 16 + g], psum[mt * 2 + 0]);
        atomicAdd(&ssum[wmA * 32 + mt * 16 + g + 8], psum[mt * 2 + 1]);
    }
    __syncthreads();
    if (tid < 64) ssum[tid] = 1.f / ssum[tid];
    __syncthreads();

    // prefetch V chunk 0 while writing attns
#pragma unroll
    for (int j = 0; j < 4; j++) {
        int cid = tid + 256 * j;
        int row = cid >> 3, c = cid & 7;
        cpa16(sKV + row * 144 + c * 16,
              qkv + ((size_t)(b * SS + row)) * QS + 1024 + h * 64 + c * 8);
    }
    asm volatile("cp.async.commit_group;");

    // write normalized P (fp32, streaming) to attns
    {
        float* dst = attns + (((size_t)(h * BB + b)) * SS + s0) * SS;
        for (int i = tid; i < 8192; i += 256) {
            int row = i >> 7, c4 = (i & 127) * 4;
            uint2 u = *(uint2*)(EsH + row * 520 + c4);
            float2 f0 = __half22float2(*(__half2*)&u.x);
            float2 f1 = __half22float2(*(__half2*)&u.y);
            float riv = ssum[row];
            stcs4(dst + (size_t)row * SS + c4,
                  make_float4(f0.x * riv, f0.y * riv, f1.x * riv, f1.y * riv));
        }
    }
    asm volatile("cp.async.wait_group 0;");
    __syncthreads();

    // ---- Phase B: O = (Es @ V) * rinv ----
    int wmB = wid >> 1, wnB = wid & 1;  // 4 x 2; warp tile m16 x n32
    float oacc[4][4];
#pragma unroll
    for (int j = 0; j < 4; j++)
#pragma unroll
        for (int c = 0; c < 4; c++) oacc[j][c] = 0.f;

    for (int t0 = 0; t0 < SS; t0 += 128) {
#pragma unroll
        for (int k16 = 0; k16 < 8; k16++) {
            uint32_t a[4];
            {
                int row = wmB * 16 + l15;
                ldm_x4(a, sE + row * 1040 + (t0 + k16 * 16) * 2 + l16 * 16);
            }
            uint32_t bt[2][4];
#pragma unroll
            for (int pair = 0; pair < 2; pair++) {
                int kr = k16 * 16 + l15;
                int nv = wnB * 32 + pair * 16 + l16 * 8;
                ldm_x4_t(bt[pair], sKV + kr * 144 + nv * 2);
            }
            // trans-ldmatrix register order: {b0(n-low), b1(n-low), b0(n-high), b1(n-high)}
#pragma unroll
            for (int nt = 0; nt < 4; nt++)
                mma_f16(oacc[nt], a, bt[nt >> 1][(nt & 1) * 2], bt[nt >> 1][(nt & 1) * 2 + 1]);
        }
        __syncthreads();
        if (t0 + 128 < SS) {
#pragma unroll
            for (int j = 0; j < 4; j++) {
                int cid = tid + 256 * j;
                int row = cid >> 3, c = cid & 7;
                cpa16(sKV + row * 144 + c * 16,
                      qkv + ((size_t)(b * SS + t0 + 128 + row)) * QS + 1024 + h * 64 + c * 8);
            }
            asm volatile("cp.async.commit_group;");
            asm volatile("cp.async.wait_group 0;");
            __syncthreads();
        }
    }

    // write O (fp16 heads)
    {
        int r0 = wmB * 16 + g;
        float ri0 = ssum[r0], ri1 = ssum[r0 + 8];
        size_t base0 = ((size_t)(b * SS + s0 + r0)) * DM + h * 64;
        size_t base1 = ((size_t)(b * SS + s0 + r0 + 8)) * DM + h * 64;
#pragma unroll
        for (int nt = 0; nt < 4; nt++) {
            int c = wnB * 32 + nt * 8 + 2 * t4;
            *(__half2*)(heads + base0 + c) =
                __floats2half2_rn(oacc[nt][0] * ri0, oacc[nt][1] * ri0);
            *(__half2*)(heads + base1 + c) =
                __floats2half2_rn(oacc[nt][2] * ri1, oacc[nt][3] * ri1);
        }
    }
}

// ---------------- layernorm (fp16 in, fp32 math): out_f and/or out_h ----------------
__global__ void ln_kernel(const __half* __restrict__ y, const __half* __restrict__ resid,
                          const float* __restrict__ g, const float* __restrict__ be,
                          float* __restrict__ out_f, __half* __restrict__ out_h) {
    int row = blockIdx.x;
    int tid = threadIdx.x;  // 128
    uint2 uy = ((const uint2*)(y + (size_t)row * DM))[tid];
    uint2 ur = ((const uint2*)(resid + (size_t)row * DM))[tid];
    float2 a0 = __half22float2(*(__half2*)&uy.x);
    float2 a1 = __half22float2(*(__half2*)&uy.y);
    float2 b0 = __half22float2(*(__half2*)&ur.x);
    float2 b1 = __half22float2(*(__half2*)&ur.y);
    float v0 = a0.x + b0.x, v1 = a0.y + b0.y, v2 = a1.x + b1.x, v3 = a1.y + b1.y;
    float s = v0 + v1 + v2 + v3;
    float ss = v0 * v0 + v1 * v1 + v2 * v2 + v3 * v3;
    for (int o = 16; o; o >>= 1) {
        s += __shfl_xor_sync(~0u, s, o);
        ss += __shfl_xor_sync(~0u, ss, o);
    }
    __shared__ float shs[4], shss[4];
    int w = tid >> 5, l = tid & 31;
    if (l == 0) { shs[w] = s; shss[w] = ss; }
    __syncthreads();
    s = shs[0] + shs[1] + shs[2] + shs[3];
    ss = shss[0] + shss[1] + shss[2] + shss[3];
    float mu = s * (1.f / 512.f);
    float var = fmaxf((ss - 512.f * mu * mu) * (1.f / 511.f), 0.f);
    float inv = 1.f / (sqrtf(var) + EPSLN);
    float4 gg = ((const float4*)g)[tid];
    float4 bb = ((const float4*)be)[tid];
    float o0 = (v0 - mu) * inv * gg.x + bb.x;
    float o1 = (v1 - mu) * inv * gg.y + bb.y;
    float o2 = (v2 - mu) * inv * gg.z + bb.z;
    float o3 = (v3 - mu) * inv * gg.w + bb.w;
    if (out_f)
        stcs4(out_f + (size_t)row * DM + tid * 4, make_float4(o0, o1, o2, o3));
    if (out_h) {
        __half2 h0 = __floats2half2_rn(o0, o1);
        __half2 h1 = __floats2half2_rn(o2, o3);
        uint2 u;
        u.x = *(uint32_t*)&h0;
        u.y = *(uint32_t*)&h1;
        ((uint2*)(out_h + (size_t)row * DM))[tid] = u;
    }
}

// ---------------- launch ----------------
extern "C" void kernel_launch(void* const* d_in, const int* in_sizes, int n_in,
                              void* d_out, int out_size) {
    const float* x      = (const float*)d_in[0];
    const float* w_qs   = (const float*)d_in[1];
    const float* w_ks   = (const float*)d_in[2];
    const float* w_vs   = (const float*)d_in[3];
    const float* proj_w = (const float*)d_in[4];
    const float* proj_b = (const float*)d_in[5];
    const float* ln1_g  = (const float*)d_in[6];
    const float* ln1_b  = (const float*)d_in[7];
    const float* ffn_w1 = (const float*)d_in[8];
    const float* ffn_b1 = (const float*)d_in[9];
    const float* ffn_w2 = (const float*)d_in[10];
    const float* ffn_b2 = (const float*)d_in[11];
    const float* ln2_g  = (const float*)d_in[12];
    const float* ln2_b  = (const float*)d_in[13];
    const int*   keepm  = (const int*)d_in[14];

    float* out = (float*)d_out;
    float* enc_out = out;
    float* attns   = out + ENC_ELEMS;

    __half *xch, *qkvh, *headsh, *tmph, *attnouth, *ffnh, *wqkvT, *projwT, *w1T, *w2T;
    int *idx, *nk;
    cudaGetSymbolAddress((void**)&xch, g_xch);
    cudaGetSymbolAddress((void**)&qkvh, g_qkvh);
    cudaGetSymbolAddress((void**)&headsh, g_headsh);
    cudaGetSymbolAddress((void**)&tmph, g_tmph);
    cudaGetSymbolAddress((void**)&attnouth, g_attnouth);
    cudaGetSymbolAddress((void**)&ffnh, g_ffnh);
    cudaGetSymbolAddress((void**)&wqkvT, g_wqkvT);
    cudaGetSymbolAddress((void**)&projwT, g_projwT);
    cudaGetSymbolAddress((void**)&w1T, g_w1T);
    cudaGetSymbolAddress((void**)&w2T, g_w2T);
    cudaGetSymbolAddress((void**)&idx, g_idx);
    cudaGetSymbolAddress((void**)&nk, g_nkeep);

    static int smem_set = 0;
    if (!smem_set) {
        cudaFuncSetAttribute(attention_h, cudaFuncAttributeMaxDynamicSharedMemorySize, ATT_SMEM);
        cudaFuncSetAttribute(hgemm, cudaFuncAttributeMaxDynamicSharedMemorySize, HSM_TOTAL);
        smem_set = 1;
    }

    // launch order tuned so ncu (-s 5 -c 1) captures attention_h (index 5)
    // 0: weight transposes (fused)
    prep_weights<<<dim3(64, 64, 3), dim3(32, 8)>>>(proj_w, ffn_w1, ffn_w2, projwT, w1T, w2T);
    // 1: qkv weight pack
    pack_wqkv_t<<<(1536 * 512) / 256, 256>>>(w_qs, w_ks, w_vs, wqkvT);
    // 2: skipper
    skipper_scan<<<BB, SS>>>(keepm, idx, nk);
    // 3: gather (fp16 only)
    gather_kernel<<<MTOT, 128>>>(x, idx, nk, xch);
    // 4: fused QKV projection -> fp16 qkv
    hgemm<<<dim3(1536 / 128, MTOT / 128), 256, HSM_TOTAL>>>(
        xch, wqkvT, nullptr, qkvh, MTOT, 1536, DM, nullptr, 0);
    // 5: fp16 attention (writes attns fp32 + heads fp16)  <-- profiled
    attention_h<<<dim3(BB * NH, SS / 64), 256, ATT_SMEM>>>(qkvh, nk, attns, headsh);
    // 6: output projection (fp16 out)
    hgemm<<<dim3(DM / 128, MTOT / 128), 256, HSM_TOTAL>>>(
        headsh, projwT, nullptr, tmph, MTOT, DM, DM, proj_b, 0);
    // 7: LN1 (fp16 out only)
    ln_kernel<<<MTOT, 128>>>(tmph, xch, ln1_g, ln1_b, nullptr, attnouth);
    // 8: FFN1 (relu, fp16 out)
    hgemm<<<dim3(DINNER / 128, MTOT / 128), 256, HSM_TOTAL>>>(
        attnouth, w1T, nullptr, ffnh, MTOT, DINNER, DM, ffn_b1, 1);
    // 9: FFN2 (fp16 out)
    hgemm<<<dim3(DM / 128, MTOT / 128), 256, HSM_TOTAL>>>(
        ffnh, w2T, nullptr, tmph, MTOT, DM, DINNER, ffn_b2, 0);
    // 10: LN2 -> enc_out fp32
    ln_kernel<<<MTOT, 128>>>(tmph, attnouth, ln2_g, ln2_b, enc_out, nullptr);
}

// round 10
// speedup vs baseline: 10.2824x; 1.0275x over previous
#include <cuda_runtime.h>
#include <cuda_fp16.h>
#include <math.h>
#include <stdint.h>

// ---------------- problem constants ----------------
#define BB 32
#define SS 512
#define DM 512
#define NH 8
#define DK 64
#define DINNER 2048
#define MTOT (BB * SS)              // 16384 rows
#define ENC_ELEMS (BB * SS * DM)    // 8388608
#define EPSLN 1e-3f

// ---------------- scratch (device globals; no allocation allowed) ----------------
__device__ __half g_xch[MTOT * DM];         // compacted input fp16 (GEMM A + LN1 residual)
__device__ __half g_qkvh[MTOT * 3 * DM];    // merged q|k|v  [row][1536] fp16
__device__ __half g_headsh[MTOT * DM];      // attn heads (fp16)
__device__ __half g_tmph[MTOT * DM];        // pre-LN gemm out (fp16, reused)
__device__ __half g_attnouth[MTOT * DM];    // LN1 output (fp16)
__device__ __half g_ffnh[MTOT * DINNER];    // FFN hidden (fp16, relu'd)
__device__ __half g_wqkvT[1536 * DM];       // [n][k] fp16
__device__ __half g_projwT[DM * DM];
__device__ __half g_w1T[DINNER * DM];
__device__ __half g_w2T[DM * DINNER];
__device__ int    g_idx[BB * SS];
__device__ int    g_nkeep[BB];

// ---------------- helpers ----------------
__device__ __forceinline__ void cpa16(uint32_t dst, const void* src) {
    asm volatile("cp.async.cg.shared.global [%0], [%1], 16;" :: "r"(dst), "l"(src));
}
__device__ __forceinline__ void ldm_x4(uint32_t* r, uint32_t addr) {
    asm volatile("ldmatrix.sync.aligned.m8n8.x4.shared.b16 {%0,%1,%2,%3}, [%4];"
                 : "=r"(r[0]), "=r"(r[1]), "=r"(r[2]), "=r"(r[3]) : "r"(addr));
}
__device__ __forceinline__ void ldm_x4_t(uint32_t* r, uint32_t addr) {
    asm volatile("ldmatrix.sync.aligned.m8n8.x4.trans.shared.b16 {%0,%1,%2,%3}, [%4];"
                 : "=r"(r[0]), "=r"(r[1]), "=r"(r[2]), "=r"(r[3]) : "r"(addr));
}
__device__ __forceinline__ void mma_f16(float* d, const uint32_t* a, uint32_t b0, uint32_t b1) {
    asm volatile(
        "mma.sync.aligned.m16n8k16.row.col.f32.f16.f16.f32 "
        "{%0,%1,%2,%3}, {%4,%5,%6,%7}, {%8,%9}, {%0,%1,%2,%3};"
        : "+f"(d[0]), "+f"(d[1]), "+f"(d[2]), "+f"(d[3])
        : "r"(a[0]), "r"(a[1]), "r"(a[2]), "r"(a[3]), "r"(b0), "r"(b1));
}
__device__ __forceinline__ float fast_exp(float x) {
    float t = x * 1.4426950408889634f;
    float z = t + 12582912.0f;
    int   m = __float_as_int(z) - 0x4B400000;
    float f = t - (z - 12582912.0f);
    float p = 1.3333558146e-3f;
    p = fmaf(p, f, 9.6181291076e-3f);
    p = fmaf(p, f, 5.5504108665e-2f);
    p = fmaf(p, f, 2.4022650696e-1f);
    p = fmaf(p, f, 6.9314718056e-1f);
    p = fmaf(p, f, 1.0f);
    return __int_as_float(__float_as_int(p) + (m << 23));
}
__device__ __forceinline__ uint32_t smem_u32(const void* p) {
    uint32_t a;
    asm("{ .reg .u64 t; cvta.to.shared.u64 t, %1; cvt.u32.u64 %0, t; }" : "=r"(a) : "l"(p));
    return a;
}
__device__ __forceinline__ void stcs4(float* p, float4 v) {
    asm volatile("st.global.cs.v4.f32 [%0], {%1,%2,%3,%4};"
                 :: "l"(p), "f"(v.x), "f"(v.y), "f"(v.z), "f"(v.w) : "memory");
}

// ---------------- weight prep: 3 transposes fused (one launch) ----------------
__global__ void prep_weights(const float* __restrict__ proj_w, const float* __restrict__ w1,
                             const float* __restrict__ w2, __half* __restrict__ projwT,
                             __half* __restrict__ w1T, __half* __restrict__ w2T) {
    __shared__ float t[32][33];
    int z = blockIdx.z;
    const float* in;
    __half* out;
    int R, C;
    if (z == 0)      { in = proj_w; out = projwT; R = DM;     C = DM; }
    else if (z == 1) { in = w1;     out = w1T;    R = DM;     C = DINNER; }
    else             { in = w2;     out = w2T;    R = DINNER; C = DM; }
    int c0 = blockIdx.x * 32, r0 = blockIdx.y * 32;
    if (c0 >= C || r0 >= R) return;
    int x = threadIdx.x, y = threadIdx.y;  // 32 x 8
#pragma unroll
    for (int j = 0; j < 32; j += 8)
        t[y + j][x] = in[(size_t)(r0 + y + j) * C + c0 + x];
    __syncthreads();
#pragma unroll
    for (int j = 0; j < 32; j += 8)
        out[(size_t)(c0 + y + j) * R + r0 + x] = __float2half_rn(t[x][y + j]);
}

// pack per-head weights [H, D, 64] x3 -> transposed [1536][512] fp16
__global__ void pack_wqkv_t(const float* __restrict__ wq, const float* __restrict__ wk,
                            const float* __restrict__ wv, __half* __restrict__ wp) {
    int i = blockIdx.x * 256 + threadIdx.x;  // over 1536*512
    int n = i >> 9;
    int d = i & 511;
    int sel = n >> 9;
    int nn = n & 511;
    int h = nn >> 6, kk = nn & 63;
    const float* w = (sel == 0) ? wq : (sel == 1) ? wk : wv;
    wp[i] = __float2half_rn(w[(h * DM + d) * DK + kk]);
}

// ---------------- skipper ----------------
__global__ void skipper_scan(const int* __restrict__ keep, int* __restrict__ idx,
                             int* __restrict__ nkeep) {
    int b = blockIdx.x, t = threadIdx.x;
    __shared__ int sh[SS];
    int v = keep[b * SS + t] > 0;
    sh[t] = v;
    __syncthreads();
    for (int off = 1; off < SS; off <<= 1) {
        int x = (t >= off) ? sh[t - off] : 0;
        __syncthreads();
        sh[t] += x;
        __syncthreads();
    }
    int incl = sh[t];
    if (v) idx[b * SS + incl - 1] = t;
    if (t == SS - 1) nkeep[b] = incl;
}

// 2 rows per 256-thread block
__global__ void gather_kernel(const float* __restrict__ x, const int* __restrict__ idx,
                              const int* __restrict__ nkeep, __half* __restrict__ xch) {
    int bs = blockIdx.x * 2 + (threadIdx.x >> 7);
    int t = threadIdx.x & 127;
    int b = bs >> 9, s = bs & 511;
    int nk = nkeep[b];
    float4 v = make_float4(0.f, 0.f, 0.f, 0.f);
    if (s < nk)
        v = ((const float4*)(x + ((size_t)b * SS + idx[b * SS + s]) * DM))[t];
    __half2 h0 = __floats2half2_rn(v.x, v.y);
    __half2 h1 = __floats2half2_rn(v.z, v.w);
    uint2 u;
    u.x = *(uint32_t*)&h0;
    u.y = *(uint32_t*)&h1;
    ((uint2*)(xch + (size_t)bs * DM))[t] = u;
}

// ---------------- fp16 tensor-core GEMM (128x128 tile, BK=64, 3-stage) ----------------
#define HSM_TOTAL 98304   // 3 x (16K A + 16K B)

__global__ void __launch_bounds__(256, 2) hgemm(
    const __half* __restrict__ A, const __half* __restrict__ Bt,
    float* __restrict__ Cf, __half* __restrict__ Ch,
    int M, int N, int K, const float* __restrict__ bias, int relu) {
    extern __shared__ __align__(128) char smc[];
    uint32_t sbase = smem_u32(smc);     // A bufs: 0..49152, B bufs: 49152..98304

    int tid = threadIdx.x;
    int wid = tid >> 5, lane = tid & 31;
    int g = lane >> 2, t4 = lane & 3;
    int l15 = lane & 15, l16 = lane >> 4;
    int wm = wid >> 2, wn = wid & 3;
    int rowBase = blockIdx.y * 128;
    int colBase = blockIdx.x * 128;

    float acc[4][4][4];
#pragma unroll
    for (int i = 0; i < 4; i++)
#pragma unroll
        for (int j = 0; j < 4; j++)
#pragma unroll
            for (int c = 0; c < 4; c++) acc[i][j][c] = 0.f;

    const int nc = K / 64;

    auto load_tile = [&](int kt, int buf) {
        int k0 = kt * 64;
#pragma unroll
        for (int j = 0; j < 4; j++) {
            int cid = tid + 256 * j;
            int row = cid >> 3, c = cid & 7;
            uint32_t off = row * 128 + ((c ^ (row & 7)) << 4);
            cpa16(sbase + buf * 16384 + off,
                  A + (size_t)(rowBase + row) * K + k0 + c * 8);
            cpa16(sbase + 49152 + buf * 16384 + off,
                  Bt + (size_t)(colBase + row) * K + k0 + c * 8);
        }
        asm volatile("cp.async.commit_group;");
    };

    load_tile(0, 0);
    if (nc > 1) load_tile(1, 1);

    for (int kt = 0; kt < nc; kt++) {
        int buf = kt % 3;
        if (kt + 2 < nc) {
            load_tile(kt + 2, (kt + 2) % 3);
            asm volatile("cp.async.wait_group 2;");
        } else if (kt + 1 < nc) {
            asm volatile("cp.async.wait_group 1;");
        } else {
            asm volatile("cp.async.wait_group 0;");
        }
        __syncthreads();

        uint32_t aBase = sbase + buf * 16384;
        uint32_t bBase = sbase + 49152 + buf * 16384;
#pragma unroll
        for (int ks = 0; ks < 4; ks++) {
            int ch = 2 * ks + l16;
            uint32_t a[4][4];
#pragma unroll
            for (int mt = 0; mt < 4; mt++) {
                int row = wm * 64 + mt * 16 + l15;
                ldm_x4(a[mt], aBase + row * 128 + ((ch ^ (row & 7)) << 4));
            }
            uint32_t bq[2][4];
#pragma unroll
            for (int bt = 0; bt < 2; bt++) {
                int row = wn * 32 + bt * 16 + l15;
                ldm_x4(bq[bt], bBase + row * 128 + ((ch ^ (row & 7)) << 4));
            }
#pragma unroll
            for (int mt = 0; mt < 4; mt++)
#pragma unroll
                for (int nt = 0; nt < 4; nt++)
                    mma_f16(acc[mt][nt], a[mt], bq[nt >> 1][nt & 1], bq[nt >> 1][2 + (nt & 1)]);
        }
        __syncthreads();
    }

#pragma unroll
    for (int mt = 0; mt < 4; mt++) {
        int r0 = rowBase + wm * 64 + mt * 16 + g;
#pragma unroll
        for (int nt = 0; nt < 4; nt++) {
            int c = colBase + wn * 32 + nt * 8 + 2 * t4;
            float b0 = bias ? __ldg(bias + c) : 0.f;
            float b1 = bias ? __ldg(bias + c + 1) : 0.f;
            float v0 = acc[mt][nt][0] + b0, v1 = acc[mt][nt][1] + b1;
            float v2 = acc[mt][nt][2] + b0, v3 = acc[mt][nt][3] + b1;
            if (relu) {
                v0 = fmaxf(v0, 0.f); v1 = fmaxf(v1, 0.f);
                v2 = fmaxf(v2, 0.f); v3 = fmaxf(v3, 0.f);
            }
            if (Cf) {
                *(float2*)(Cf + (size_t)r0 * N + c) = make_float2(v0, v1);
                *(float2*)(Cf + (size_t)(r0 + 8) * N + c) = make_float2(v2, v3);
            }
            if (Ch) {
                *(__half2*)(Ch + (size_t)r0 * N + c) = __floats2half2_rn(v0, v1);
                *(__half2*)(Ch + (size_t)(r0 + 8) * N + c) = __floats2half2_rn(v2, v3);
            }
        }
    }
}

// ---------------- fp16 tensor-core attention ----------------
// block = (b,h) x 64-row s-tile, 256 threads / 8 warps, 2 CTA/SM.
// smem (halves strides): Q[64][72], KV[128][72], Es[64][520] fp16, ssum[64] fp32
#define SQ_OFF 0
#define SKV_OFF 9216
#define SE_OFF 27648
#define SSUM_OFF 94208
#define ATT_SMEM 94464

__global__ void __launch_bounds__(256, 2) attention_h(
    const __half* __restrict__ qkv, const int* __restrict__ nkeep,
    float* __restrict__ attns, __half* __restrict__ heads) {
    extern __shared__ __align__(128) char smc[];
    uint32_t sbase = smem_u32(smc);
    uint32_t sQ = sbase + SQ_OFF;
    uint32_t sKV = sbase + SKV_OFF;
    uint32_t sE = sbase + SE_OFF;
    float* ssum = (float*)(smc + SSUM_OFF);
    __half* EsH = (__half*)(smc + SE_OFF);

    int bh = blockIdx.x;
    int b = bh >> 3, h = bh & 7;
    int s0 = blockIdx.y * 64;
    int tid = threadIdx.x;
    int wid = tid >> 5, lane = tid & 31;
    int g = lane >> 2, t4 = lane & 3;
    int l15 = lane & 15, l16 = lane >> 4;
    int nk = nkeep[b];
    const float sc = 0.04419417382415922f;  // 1/sqrt(512)
    const int QS = 3 * DM;                  // 1536 halves per row

    if (tid < 64) ssum[tid] = 0.f;

    // async-load Q tile (64 rows x 64 halves)
#pragma unroll
    for (int j = 0; j < 2; j++) {
        int cid = tid + 256 * j;
        int row = cid >> 3, c = cid & 7;
        cpa16(sQ + row * 144 + c * 16,
              qkv + ((size_t)(b * SS + s0 + row)) * QS + h * 64 + c * 8);
    }
    // async-load K chunk 0 (128 rows x 64 halves)
#pragma unroll
    for (int j = 0; j < 4; j++) {
        int cid = tid + 256 * j;
        int row = cid >> 3, c = cid & 7;
        cpa16(sKV + row * 144 + c * 16,
              qkv + ((size_t)(b * SS + row)) * QS + 512 + h * 64 + c * 8);
    }
    asm volatile("cp.async.commit_group;");
    asm volatile("cp.async.wait_group 0;");
    __syncthreads();

    // ---- Phase A: exp(QK^T * sc) -> Es fp16, partial row sums in regs ----
    int wmA = wid >> 2, wnA = wid & 3;  // 2 x 4; warp tile m32 x n32
    float psum[4] = {0.f, 0.f, 0.f, 0.f};

    for (int t0 = 0; t0 < SS; t0 += 128) {
        float acc[2][4][4];
#pragma unroll
        for (int i = 0; i < 2; i++)
#pragma unroll
            for (int j = 0; j < 4; j++)
#pragma unroll
                for (int c = 0; c < 4; c++) acc[i][j][c] = 0.f;

#pragma unroll
        for (int ks = 0; ks < 4; ks++) {
            uint32_t a[2][4];
#pragma unroll
            for (int mt = 0; mt < 2; mt++) {
                int row = wmA * 32 + mt * 16 + l15;
                ldm_x4(a[mt], sQ + row * 144 + ks * 32 + l16 * 16);
            }
            uint32_t bq[2][4];
#pragma unroll
            for (int bt = 0; bt < 2; bt++) {
                int row = wnA * 32 + bt * 16 + l15;
                ldm_x4(bq[bt], sKV + row * 144 + ks * 32 + l16 * 16);
            }
#pragma unroll
            for (int mt = 0; mt < 2; mt++)
#pragma unroll
                for (int nt = 0; nt < 4; nt++)
                    mma_f16(acc[mt][nt], a[mt], bq[nt >> 1][nt & 1], bq[nt >> 1][2 + (nt & 1)]);
        }
        __syncthreads();  // done reading K chunk

        // prefetch next K chunk
        if (t0 + 128 < SS) {
#pragma unroll
            for (int j = 0; j < 4; j++) {
                int cid = tid + 256 * j;
                int row = cid >> 3, c = cid & 7;
                cpa16(sKV + row * 144 + c * 16,
                      qkv + ((size_t)(b * SS + t0 + 128 + row)) * QS + 512 + h * 64 + c * 8);
            }
            asm volatile("cp.async.commit_group;");
        }

        // exp + mask + store fp16 + accumulate partial row sums
#pragma unroll
        for (int mt = 0; mt < 2; mt++) {
            int r0 = wmA * 32 + mt * 16 + g;
#pragma unroll
            for (int nt = 0; nt < 4; nt++) {
                int col = t0 + wnA * 32 + nt * 8 + 2 * t4;
                float e0 = (col     < nk) ? fast_exp(acc[mt][nt][0] * sc) : 0.f;
                float e1 = (col + 1 < nk) ? fast_exp(acc[mt][nt][1] * sc) : 0.f;
                float e2 = (col     < nk) ? fast_exp(acc[mt][nt][2] * sc) : 0.f;
                float e3 = (col + 1 < nk) ? fast_exp(acc[mt][nt][3] * sc) : 0.f;
                *(__half2*)(EsH + r0 * 520 + col) = __floats2half2_rn(e0, e1);
                *(__half2*)(EsH + (r0 + 8) * 520 + col) = __floats2half2_rn(e2, e3);
                psum[mt * 2 + 0] += e0 + e1;
                psum[mt * 2 + 1] += e2 + e3;
            }
        }

        if (t0 + 128 < SS) {
            asm volatile("cp.async.wait_group 0;");
            __syncthreads();
        }
    }

    // merge partial sums
#pragma unroll
    for (int mt = 0; mt < 2; mt++) {
        atomicAdd(&ssum[wmA * 32 + mt * 16 + g], psum[mt * 2 + 0]);
        atomicAdd(&ssum[wmA * 32 + mt * 16 + g + 8], psum[mt * 2 + 1]);
    }
    __syncthreads();
    if (tid < 64) ssum[tid] = 1.f / ssum[tid];
    __syncthreads();

    // attns chunk writer: 64 rows x 128 cols fp32, streaming
    float* attn_base = attns + (((size_t)(h * BB + b)) * SS + s0) * SS;
    auto write_chunk = [&](int t0) {
        for (int i = tid; i < 2048; i += 256) {
            int row = i >> 5, c4 = (i & 31) * 4;
            uint2 u = *(uint2*)(EsH + row * 520 + t0 + c4);
            float2 f0 = __half22float2(*(__half2*)&u.x);
            float2 f1 = __half22float2(*(__half2*)&u.y);
            float riv = ssum[row];
            stcs4(attn_base + (size_t)row * SS + t0 + c4,
                  make_float4(f0.x * riv, f0.y * riv, f1.x * riv, f1.y * riv));
        }
    };

    // prefetch V chunk 0; overlap with attns chunk-0 write
#pragma unroll
    for (int j = 0; j < 4; j++) {
        int cid = tid + 256 * j;
        int row = cid >> 3, c = cid & 7;
        cpa16(sKV + row * 144 + c * 16,
              qkv + ((size_t)(b * SS + row)) * QS + 1024 + h * 64 + c * 8);
    }
    asm volatile("cp.async.commit_group;");
    write_chunk(0);
    asm volatile("cp.async.wait_group 0;");
    __syncthreads();

    // ---- Phase B: O = (Es @ V) * rinv, attns writes interleaved ----
    int wmB = wid >> 1, wnB = wid & 1;  // 4 x 2; warp tile m16 x n32
    float oacc[4][4];
#pragma unroll
    for (int j = 0; j < 4; j++)
#pragma unroll
        for (int c = 0; c < 4; c++) oacc[j][c] = 0.f;

    for (int ci = 0; ci < 4; ci++) {
        int t0 = ci * 128;
#pragma unroll
        for (int k16 = 0; k16 < 8; k16++) {
            uint32_t a[4];
            {
                int row = wmB * 16 + l15;
                ldm_x4(a, sE + row * 1040 + (t0 + k16 * 16) * 2 + l16 * 16);
            }
            uint32_t bt[2][4];
#pragma unroll
            for (int pair = 0; pair < 2; pair++) {
                int kr = k16 * 16 + l15;
                int nv = wnB * 32 + pair * 16 + l16 * 8;
                ldm_x4_t(bt[pair], sKV + kr * 144 + nv * 2);
            }
            // trans-ldmatrix register order: {b0(n-low), b1(n-low), b0(n-high), b1(n-high)}
#pragma unroll
            for (int nt = 0; nt < 4; nt++)
                mma_f16(oacc[nt], a, bt[nt >> 1][(nt & 1) * 2], bt[nt >> 1][(nt & 1) * 2 + 1]);
        }
        __syncthreads();
        if (ci < 3) {
            // prefetch next V chunk, then hide attns store of chunk ci+1 under it
#pragma unroll
            for (int j = 0; j < 4; j++) {
                int cid = tid + 256 * j;
                int row = cid >> 3, c = cid & 7;
                cpa16(sKV + row * 144 + c * 16,
                      qkv + ((size_t)(b * SS + t0 + 128 + row)) * QS + 1024 + h * 64 + c * 8);
            }
            asm volatile("cp.async.commit_group;");
            write_chunk(t0 + 128);
            asm volatile("cp.async.wait_group 0;");
            __syncthreads();
        }
    }

    // write O (fp16 heads)
    {
        int r0 = wmB * 16 + g;
        float ri0 = ssum[r0], ri1 = ssum[r0 + 8];
        size_t base0 = ((size_t)(b * SS + s0 + r0)) * DM + h * 64;
        size_t base1 = ((size_t)(b * SS + s0 + r0 + 8)) * DM + h * 64;
#pragma unroll
        for (int nt = 0; nt < 4; nt++) {
            int c = wnB * 32 + nt * 8 + 2 * t4;
            *(__half2*)(heads + base0 + c) =
                __floats2half2_rn(oacc[nt][0] * ri0, oacc[nt][1] * ri0);
            *(__half2*)(heads + base1 + c) =
                __floats2half2_rn(oacc[nt][2] * ri1, oacc[nt][3] * ri1);
        }
    }
}

// ---------------- layernorm (fp16 in, fp32 math): out_f and/or out_h ----------------
__global__ void ln_kernel(const __half* __restrict__ y, const __half* __restrict__ resid,
                          const float* __restrict__ g, const float* __restrict__ be,
                          float* __restrict__ out_f, __half* __restrict__ out_h) {
    int row = blockIdx.x;
    int tid = threadIdx.x;  // 128
    uint2 uy = ((const uint2*)(y + (size_t)row * DM))[tid];
    uint2 ur = ((const uint2*)(resid + (size_t)row * DM))[tid];
    float2 a0 = __half22float2(*(__half2*)&uy.x);
    float2 a1 = __half22float2(*(__half2*)&uy.y);
    float2 b0 = __half22float2(*(__half2*)&ur.x);
    float2 b1 = __half22float2(*(__half2*)&ur.y);
    float v0 = a0.x + b0.x, v1 = a0.y + b0.y, v2 = a1.x + b1.x, v3 = a1.y + b1.y;
    float s = v0 + v1 + v2 + v3;
    float ss = v0 * v0 + v1 * v1 + v2 * v2 + v3 * v3;
    for (int o = 16; o; o >>= 1) {
        s += __shfl_xor_sync(~0u, s, o);
        ss += __shfl_xor_sync(~0u, ss, o);
    }
    __shared__ float shs[4], shss[4];
    int w = tid >> 5, l = tid & 31;
    if (l == 0) { shs[w] = s; shss[w] = ss; }
    __syncthreads();
    s = shs[0] + shs[1] + shs[2] + shs[3];
    ss = shss[0] + shss[1] + shss[2] + shss[3];
    float mu = s * (1.f / 512.f);
    float var = fmaxf((ss - 512.f * mu * mu) * (1.f / 511.f), 0.f);
    float inv = 1.f / (sqrtf(var) + EPSLN);
    float4 gg = ((const float4*)g)[tid];
    float4 bb = ((const float4*)be)[tid];
    float o0 = (v0 - mu) * inv * gg.x + bb.x;
    float o1 = (v1 - mu) * inv * gg.y + bb.y;
    float o2 = (v2 - mu) * inv * gg.z + bb.z;
    float o3 = (v3 - mu) * inv * gg.w + bb.w;
    if (out_f)
        stcs4(out_f + (size_t)row * DM + tid * 4, make_float4(o0, o1, o2, o3));
    if (out_h) {
        __half2 h0 = __floats2half2_rn(o0, o1);
        __half2 h1 = __floats2half2_rn(o2, o3);
        uint2 u;
        u.x = *(uint32_t*)&h0;
        u.y = *(uint32_t*)&h1;
        ((uint2*)(out_h + (size_t)row * DM))[tid] = u;
    }
}

// ---------------- launch ----------------
extern "C" void kernel_launch(void* const* d_in, const int* in_sizes, int n_in,
                              void* d_out, int out_size) {
    const float* x      = (const float*)d_in[0];
    const float* w_qs   = (const float*)d_in[1];
    const float* w_ks   = (const float*)d_in[2];
    const float* w_vs   = (const float*)d_in[3];
    const float* proj_w = (const float*)d_in[4];
    const float* proj_b = (const float*)d_in[5];
    const float* ln1_g  = (const float*)d_in[6];
    const float* ln1_b  = (const float*)d_in[7];
    const float* ffn_w1 = (const float*)d_in[8];
    const float* ffn_b1 = (const float*)d_in[9];
    const float* ffn_w2 = (const float*)d_in[10];
    const float* ffn_b2 = (const float*)d_in[11];
    const float* ln2_g  = (const float*)d_in[12];
    const float* ln2_b  = (const float*)d_in[13];
    const int*   keepm  = (const int*)d_in[14];

    float* out = (float*)d_out;
    float* enc_out = out;
    float* attns   = out + ENC_ELEMS;

    __half *xch, *qkvh, *headsh, *tmph, *attnouth, *ffnh, *wqkvT, *projwT, *w1T, *w2T;
    int *idx, *nk;
    cudaGetSymbolAddress((void**)&xch, g_xch);
    cudaGetSymbolAddress((void**)&qkvh, g_qkvh);
    cudaGetSymbolAddress((void**)&headsh, g_headsh);
    cudaGetSymbolAddress((void**)&tmph, g_tmph);
    cudaGetSymbolAddress((void**)&attnouth, g_attnouth);
    cudaGetSymbolAddress((void**)&ffnh, g_ffnh);
    cudaGetSymbolAddress((void**)&wqkvT, g_wqkvT);
    cudaGetSymbolAddress((void**)&projwT, g_projwT);
    cudaGetSymbolAddress((void**)&w1T, g_w1T);
    cudaGetSymbolAddress((void**)&w2T, g_w2T);
    cudaGetSymbolAddress((void**)&idx, g_idx);
    cudaGetSymbolAddress((void**)&nk, g_nkeep);

    static int smem_set = 0;
    if (!smem_set) {
        cudaFuncSetAttribute(attention_h, cudaFuncAttributeMaxDynamicSharedMemorySize, ATT_SMEM);
        cudaFuncSetAttribute(hgemm, cudaFuncAttributeMaxDynamicSharedMemorySize, HSM_TOTAL);
        smem_set = 1;
    }

    // 0: weight transposes (fused)
    prep_weights<<<dim3(64, 64, 3), dim3(32, 8)>>>(proj_w, ffn_w1, ffn_w2, projwT, w1T, w2T);
    // 1: qkv weight pack
    pack_wqkv_t<<<(1536 * 512) / 256, 256>>>(w_qs, w_ks, w_vs, wqkvT);
    // 2: skipper
    skipper_scan<<<BB, SS>>>(keepm, idx, nk);
    // 3: gather (fp16 only)
    gather_kernel<<<MTOT / 2, 256>>>(x, idx, nk, xch);
    // 4: fused QKV projection -> fp16 qkv
    hgemm<<<dim3(1536 / 128, MTOT / 128), 256, HSM_TOTAL>>>(
        xch, wqkvT, nullptr, qkvh, MTOT, 1536, DM, nullptr, 0);
    // 5: fp16 attention (writes attns fp32 + heads fp16)
    attention_h<<<dim3(BB * NH, SS / 64), 256, ATT_SMEM>>>(qkvh, nk, attns, headsh);
    // 6: output projection (fp16 out)
    hgemm<<<dim3(DM / 128, MTOT / 128), 256, HSM_TOTAL>>>(
        headsh, projwT, nullptr, tmph, MTOT, DM, DM, proj_b, 0);
    // 7: LN1 (fp16 out only)
    ln_kernel<<<MTOT, 128>>>(tmph, xch, ln1_g, ln1_b, nullptr, attnouth);
    // 8: FFN1 (relu, fp16 out)
    hgemm<<<dim3(DINNER / 128, MTOT / 128), 256, HSM_TOTAL>>>(
        attnouth, w1T, nullptr, ffnh, MTOT, DINNER, DM, ffn_b1, 1);
    // 9: FFN2 (fp16 out)
    hgemm<<<dim3(DM / 128, MTOT / 128), 256, HSM_TOTAL>>>(
        ffnh, w2T, nullptr, tmph, MTOT, DM, DINNER, ffn_b2, 0);
    // 10: LN2 -> enc_out fp32
    ln_kernel<<<MTOT, 128>>>(tmph, attnouth, ln2_g, ln2_b, enc_out, nullptr);
}